// round 2
// baseline (speedup 1.0000x reference)
#include <cuda_runtime.h>
#include <cuda_bf16.h>
#include <math.h>

// Problem constants
#define BATCH 2
#define SEQ 2048
#define DMODEL 1024
#define NHEADS 16
#define HDIM 64
#define N3 (3 * DMODEL)
#define ROWS (BATCH * SEQ)   // 4096

// Scratch (static device allocations are allowed)
__device__ float g_qkv[(size_t)ROWS * N3];      // [4096, 3072]
__device__ float g_attn[(size_t)ROWS * DMODEL]; // [4096, 1024]

// ---------------------------------------------------------------------------
// SGEMM: C[M,N] = A[M,K] @ B[K,N], all row-major fp32.
// 128x128 tile, BK=8, 256 threads, 8x8 per thread.
// Requires M%128==0, N%128==0, K%8==0 (true for all our shapes).
// ---------------------------------------------------------------------------
#define BM 128
#define BN 128
#define BK 8

__global__ __launch_bounds__(256, 2)
void sgemm128(const float* __restrict__ A, const float* __restrict__ Bm,
              float* __restrict__ Cm, int M, int N, int K) {
    __shared__ float As[BK][BM + 4];   // transposed A tile (pad keeps 16B align)
    __shared__ float Bs[BK][BN];

    const int tid = threadIdx.x;
    const int tx = tid & 15;
    const int ty = tid >> 4;
    const int m0 = blockIdx.y * BM;
    const int n0 = blockIdx.x * BN;

    float acc[8][8];
#pragma unroll
    for (int i = 0; i < 8; i++)
#pragma unroll
        for (int j = 0; j < 8; j++) acc[i][j] = 0.f;

    // A load mapping: one float4 per thread per tile
    const int arow = tid >> 1;        // 0..127
    const int ak   = (tid & 1) * 4;   // 0 or 4
    // B load mapping: one float4 per thread per tile
    const int bk = tid >> 5;          // 0..7
    const int bc = (tid & 31) * 4;    // 0..124

    const float* Aptr = A + (size_t)(m0 + arow) * K + ak;
    const float* Bptr = Bm + (size_t)bk * N + n0 + bc;

    for (int kt = 0; kt < K; kt += BK) {
        float4 av = *(const float4*)(Aptr + kt);
        float4 bv = *(const float4*)(Bptr + (size_t)kt * N);
        As[ak + 0][arow] = av.x;
        As[ak + 1][arow] = av.y;
        As[ak + 2][arow] = av.z;
        As[ak + 3][arow] = av.w;
        *(float4*)&Bs[bk][bc] = bv;
        __syncthreads();

#pragma unroll
        for (int kk = 0; kk < BK; kk++) {
            float a[8], b[8];
            *(float4*)(a)     = *(float4*)&As[kk][ty * 4];
            *(float4*)(a + 4) = *(float4*)&As[kk][ty * 4 + 64];
            *(float4*)(b)     = *(float4*)&Bs[kk][tx * 4];
            *(float4*)(b + 4) = *(float4*)&Bs[kk][tx * 4 + 64];
#pragma unroll
            for (int i = 0; i < 8; i++)
#pragma unroll
                for (int j = 0; j < 8; j++)
                    acc[i][j] = fmaf(a[i], b[j], acc[i][j]);
        }
        __syncthreads();
    }

#pragma unroll
    for (int i = 0; i < 8; i++) {
        int r = m0 + ((i < 4) ? (ty * 4 + i) : (64 + ty * 4 + i - 4));
        float4 v0 = make_float4(acc[i][0], acc[i][1], acc[i][2], acc[i][3]);
        float4 v1 = make_float4(acc[i][4], acc[i][5], acc[i][6], acc[i][7]);
        *(float4*)&Cm[(size_t)r * N + n0 + tx * 4]      = v0;
        *(float4*)&Cm[(size_t)r * N + n0 + 64 + tx * 4] = v1;
    }
}

// ---------------------------------------------------------------------------
// Flash attention (causal), fp32.
// Grid: (T/64, NHEADS, BATCH). Block: 256 threads.
// Q-tile = 64 rows, K-tile = 64 keys, Dh = 64.
// qkv layout: [(b*T + t), 3072] with cols [0:1024)=Q, [1024:2048)=K, [2048:3072)=V,
// head h occupying cols h*64..h*64+63 of each section.
// out: [(b*T + t), 1024] with col = h*64 + d.
// ---------------------------------------------------------------------------
#define AT_STRIDE 68                       // padded row stride (multiple of 4)
#define AT_TILE   (64 * AT_STRIDE)         // 4352 floats
#define AT_SMEM_FLOATS (3 * AT_TILE + 128)
#define AT_SMEM_BYTES  (AT_SMEM_FLOATS * 4)

__global__ __launch_bounds__(256)
void attn_kernel(const float* __restrict__ qkv, float* __restrict__ out) {
    extern __shared__ float sm[];
    float* Qs      = sm;                 // [d][q]  (transposed), stride 68
    float* KVs     = Qs + AT_TILE;       // K phase: [d][k] transposed; V phase: [k][d]
    float* Ss      = KVs + AT_TILE;      // [q][k] row-major, stride 68
    float* alpha_s = Ss + AT_TILE;       // [64]
    float* linv_s  = alpha_s + 64;       // [64]

    const int tid = threadIdx.x;
    const int tx = tid & 15;
    const int ty = tid >> 4;
    const int qb = blockIdx.x;
    const int h  = blockIdx.y;
    const int b  = blockIdx.z;
    const int q0 = qb * 64;

    const float* base = qkv + (size_t)b * SEQ * N3;
    const int qoff = h * HDIM;
    const int koff = DMODEL + h * HDIM;
    const int voff = 2 * DMODEL + h * HDIM;

    // Load Q tile transposed: Qs[d][q]
#pragma unroll
    for (int l = 0; l < 4; l++) {
        int idx = tid + l * 256;          // 0..1023
        int row = idx >> 4;               // 0..63 (query)
        int dq  = (idx & 15) * 4;         // 0..60 (d)
        float4 v = *(const float4*)(base + (size_t)(q0 + row) * N3 + qoff + dq);
        Qs[(dq + 0) * AT_STRIDE + row] = v.x;
        Qs[(dq + 1) * AT_STRIDE + row] = v.y;
        Qs[(dq + 2) * AT_STRIDE + row] = v.z;
        Qs[(dq + 3) * AT_STRIDE + row] = v.w;
    }

    float O[4][4];
#pragma unroll
    for (int i = 0; i < 4; i++)
#pragma unroll
        for (int j = 0; j < 4; j++) O[i][j] = 0.f;

    // Softmax state, held redundantly by the 4 threads of each row group
    const int srow = tid >> 2;   // 0..63
    const int sseg = tid & 3;    // 0..3
    float m_r = -1e30f, l_r = 0.f;

    for (int jt = 0; jt <= qb; jt++) {
        const int k0 = jt * 64;

        // Load K tile transposed: KVs[d][k]
#pragma unroll
        for (int l = 0; l < 4; l++) {
            int idx = tid + l * 256;
            int row = idx >> 4;            // key index
            int dq  = (idx & 15) * 4;
            float4 v = *(const float4*)(base + (size_t)(k0 + row) * N3 + koff + dq);
            KVs[(dq + 0) * AT_STRIDE + row] = v.x;
            KVs[(dq + 1) * AT_STRIDE + row] = v.y;
            KVs[(dq + 2) * AT_STRIDE + row] = v.z;
            KVs[(dq + 3) * AT_STRIDE + row] = v.w;
        }
        __syncthreads();

        // GEMM1: S[q][k] = sum_d Q[q][d] * K[k][d]
        float s[4][4];
#pragma unroll
        for (int i = 0; i < 4; i++)
#pragma unroll
            for (int j = 0; j < 4; j++) s[i][j] = 0.f;

#pragma unroll
        for (int kk = 0; kk < 64; kk++) {
            float4 a = *(float4*)&Qs[kk * AT_STRIDE + ty * 4];
            float4 bb = *(float4*)&KVs[kk * AT_STRIDE + tx * 4];
            s[0][0] = fmaf(a.x, bb.x, s[0][0]); s[0][1] = fmaf(a.x, bb.y, s[0][1]);
            s[0][2] = fmaf(a.x, bb.z, s[0][2]); s[0][3] = fmaf(a.x, bb.w, s[0][3]);
            s[1][0] = fmaf(a.y, bb.x, s[1][0]); s[1][1] = fmaf(a.y, bb.y, s[1][1]);
            s[1][2] = fmaf(a.y, bb.z, s[1][2]); s[1][3] = fmaf(a.y, bb.w, s[1][3]);
            s[2][0] = fmaf(a.z, bb.x, s[2][0]); s[2][1] = fmaf(a.z, bb.y, s[2][1]);
            s[2][2] = fmaf(a.z, bb.z, s[2][2]); s[2][3] = fmaf(a.z, bb.w, s[2][3]);
            s[3][0] = fmaf(a.w, bb.x, s[3][0]); s[3][1] = fmaf(a.w, bb.y, s[3][1]);
            s[3][2] = fmaf(a.w, bb.z, s[3][2]); s[3][3] = fmaf(a.w, bb.w, s[3][3]);
        }

        // Scale + causal mask, write S row-major
        const bool diag = (jt == qb);
#pragma unroll
        for (int i = 0; i < 4; i++) {
            int q = ty * 4 + i;
            float4 v;
            float vv[4];
#pragma unroll
            for (int j = 0; j < 4; j++) {
                float val = s[i][j] * 0.125f;
                if (diag && (tx * 4 + j) > q) val = -1e30f;
                vv[j] = val;
            }
            v = make_float4(vv[0], vv[1], vv[2], vv[3]);
            *(float4*)&Ss[q * AT_STRIDE + tx * 4] = v;
        }
        __syncthreads();

        // Online softmax: 4 threads per row, 16 cols each
        {
            const int jb = sseg * 16;
            float mloc = -1e30f;
#pragma unroll
            for (int j = 0; j < 16; j++)
                mloc = fmaxf(mloc, Ss[srow * AT_STRIDE + jb + j]);
            mloc = fmaxf(mloc, __shfl_xor_sync(0xffffffffu, mloc, 1));
            mloc = fmaxf(mloc, __shfl_xor_sync(0xffffffffu, mloc, 2));
            float mn = fmaxf(m_r, mloc);
            float al = __expf(m_r - mn);
            float ls = 0.f;
#pragma unroll
            for (int j = 0; j < 16; j++) {
                float p = __expf(Ss[srow * AT_STRIDE + jb + j] - mn);
                Ss[srow * AT_STRIDE + jb + j] = p;
                ls += p;
            }
            ls += __shfl_xor_sync(0xffffffffu, ls, 1);
            ls += __shfl_xor_sync(0xffffffffu, ls, 2);
            l_r = l_r * al + ls;
            m_r = mn;
            if (sseg == 0) alpha_s[srow] = al;
        }
        __syncthreads();

        // Rescale O accumulators by alpha of their rows
#pragma unroll
        for (int i = 0; i < 4; i++) {
            float al = alpha_s[ty * 4 + i];
#pragma unroll
            for (int j = 0; j < 4; j++) O[i][j] *= al;
        }

        // Load V tile row-major: KVs[k][d]  (K data no longer needed)
#pragma unroll
        for (int l = 0; l < 4; l++) {
            int idx = tid + l * 256;
            int row = idx >> 4;
            int dq  = (idx & 15) * 4;
            float4 v = *(const float4*)(base + (size_t)(k0 + row) * N3 + voff + dq);
            *(float4*)&KVs[row * AT_STRIDE + dq] = v;
        }
        __syncthreads();

        // GEMM2: O[q][d] += sum_k P[q][k] * V[k][d]
#pragma unroll
        for (int kk = 0; kk < 64; kk += 4) {
            float4 a0 = *(float4*)&Ss[(ty * 4 + 0) * AT_STRIDE + kk];
            float4 a1 = *(float4*)&Ss[(ty * 4 + 1) * AT_STRIDE + kk];
            float4 a2 = *(float4*)&Ss[(ty * 4 + 2) * AT_STRIDE + kk];
            float4 a3 = *(float4*)&Ss[(ty * 4 + 3) * AT_STRIDE + kk];
            float4 b0 = *(float4*)&KVs[(kk + 0) * AT_STRIDE + tx * 4];
            float4 b1 = *(float4*)&KVs[(kk + 1) * AT_STRIDE + tx * 4];
            float4 b2 = *(float4*)&KVs[(kk + 2) * AT_STRIDE + tx * 4];
            float4 b3 = *(float4*)&KVs[(kk + 3) * AT_STRIDE + tx * 4];
#define ACC_ROW(i, av)                                              \
            O[i][0] = fmaf(av.x, b0.x, O[i][0]);                    \
            O[i][1] = fmaf(av.x, b0.y, O[i][1]);                    \
            O[i][2] = fmaf(av.x, b0.z, O[i][2]);                    \
            O[i][3] = fmaf(av.x, b0.w, O[i][3]);                    \
            O[i][0] = fmaf(av.y, b1.x, O[i][0]);                    \
            O[i][1] = fmaf(av.y, b1.y, O[i][1]);                    \
            O[i][2] = fmaf(av.y, b1.z, O[i][2]);                    \
            O[i][3] = fmaf(av.y, b1.w, O[i][3]);                    \
            O[i][0] = fmaf(av.z, b2.x, O[i][0]);                    \
            O[i][1] = fmaf(av.z, b2.y, O[i][1]);                    \
            O[i][2] = fmaf(av.z, b2.z, O[i][2]);                    \
            O[i][3] = fmaf(av.z, b2.w, O[i][3]);                    \
            O[i][0] = fmaf(av.w, b3.x, O[i][0]);                    \
            O[i][1] = fmaf(av.w, b3.y, O[i][1]);                    \
            O[i][2] = fmaf(av.w, b3.z, O[i][2]);                    \
            O[i][3] = fmaf(av.w, b3.w, O[i][3]);
            ACC_ROW(0, a0)
            ACC_ROW(1, a1)
            ACC_ROW(2, a2)
            ACC_ROW(3, a3)
#undef ACC_ROW
        }
        __syncthreads();   // before next tile overwrites KVs / Ss
    }

    // Finalize: divide by l, write out
    if (sseg == 0) linv_s[srow] = 1.f / l_r;
    __syncthreads();

    float* outp = out + ((size_t)b * SEQ + q0) * DMODEL + h * HDIM;
#pragma unroll
    for (int i = 0; i < 4; i++) {
        float inv = linv_s[ty * 4 + i];
        float4 v = make_float4(O[i][0] * inv, O[i][1] * inv,
                               O[i][2] * inv, O[i][3] * inv);
        *(float4*)(outp + (size_t)(ty * 4 + i) * DMODEL + tx * 4) = v;
    }
}

// ---------------------------------------------------------------------------
// Launch
// ---------------------------------------------------------------------------
extern "C" void kernel_launch(void* const* d_in, const int* in_sizes, int n_in,
                              void* d_out, int out_size) {
    const float* x    = (const float*)d_in[0];
    // d_in[1] = mask (tril) — causality is applied analytically in the kernel
    const float* Wqkv = (const float*)d_in[2];
    const float* Wout = (const float*)d_in[3];
    float* out = (float*)d_out;

    float *qkv, *attn;
    cudaGetSymbolAddress((void**)&qkv, g_qkv);
    cudaGetSymbolAddress((void**)&attn, g_attn);

    // 1. QKV projection: [4096,1024] @ [1024,3072]
    sgemm128<<<dim3(N3 / BN, ROWS / BM), 256>>>(x, Wqkv, qkv, ROWS, N3, DMODEL);

    // 2. Causal flash attention
    cudaFuncSetAttribute(attn_kernel, cudaFuncAttributeMaxDynamicSharedMemorySize,
                         AT_SMEM_BYTES);
    attn_kernel<<<dim3(SEQ / 64, NHEADS, BATCH), 256, AT_SMEM_BYTES>>>(qkv, attn);

    // 3. Output projection: [4096,1024] @ [1024,1024]
    sgemm128<<<dim3(DMODEL / BN, ROWS / BM), 256>>>(attn, Wout, out, ROWS, DMODEL, DMODEL);
}

// round 5
// speedup vs baseline: 1.1674x; 1.1674x over previous
#include <cuda_runtime.h>
#include <cuda_bf16.h>
#include <cstdint>
#include <math.h>

// Problem constants
#define BATCH 2
#define SEQ 2048
#define DMODEL 1024
#define NHEADS 16
#define HDIM 64
#define N3 (3 * DMODEL)
#define ROWS (BATCH * SEQ)   // 4096
#define KK3 (3 * DMODEL)     // split K' = 3072

// Scratch
__device__ float g_qkv[(size_t)ROWS * N3];            // [4096, 3072] fp32
__device__ float g_attn[(size_t)ROWS * DMODEL];       // [4096, 1024] fp32
__device__ __nv_bfloat16 g_a3[(size_t)ROWS * KK3];    // split A: [4096, 3072]
__device__ __nv_bfloat16 g_btq[(size_t)N3 * KK3];     // split-T Wqkv: [3072, 3072]
__device__ __nv_bfloat16 g_bto[(size_t)DMODEL * KK3]; // split-T Wout: [1024, 3072]

// ===========================================================================
// Helpers (sm_80-level PTX only — NO tcgen05, target is plain compute_103)
// ===========================================================================
__device__ __forceinline__ uint32_t smem_u32(const void* p) {
    uint32_t a;
    asm("{ .reg .u64 t; cvta.to.shared.u64 t, %1; cvt.u32.u64 %0, t; }"
        : "=r"(a) : "l"(p));
    return a;
}
__device__ __forceinline__ void cpasync16(uint32_t saddr, const void* gaddr) {
    asm volatile("cp.async.cg.shared.global [%0], [%1], 16;"
                 :: "r"(saddr), "l"(gaddr));
}
#define CP_COMMIT() asm volatile("cp.async.commit_group;" ::: "memory")
#define CP_WAIT1()  asm volatile("cp.async.wait_group 1;" ::: "memory")

__device__ __forceinline__ void ldsm4(uint32_t* r, uint32_t addr) {
    asm volatile("ldmatrix.sync.aligned.m8n8.x4.shared.b16 {%0,%1,%2,%3}, [%4];"
                 : "=r"(r[0]), "=r"(r[1]), "=r"(r[2]), "=r"(r[3]) : "r"(addr));
}
__device__ __forceinline__ void mma16816(float* c, const uint32_t* a, const uint32_t* b) {
    asm volatile(
        "mma.sync.aligned.m16n8k16.row.col.f32.bf16.bf16.f32 "
        "{%0,%1,%2,%3}, {%4,%5,%6,%7}, {%8,%9}, {%0,%1,%2,%3};"
        : "+f"(c[0]), "+f"(c[1]), "+f"(c[2]), "+f"(c[3])
        : "r"(a[0]), "r"(a[1]), "r"(a[2]), "r"(a[3]), "r"(b[0]), "r"(b[1]));
}

// ===========================================================================
// Split kernels: fp32 -> bf16 hi/lo, 3-term layout
// A side: [hi | hi | lo], B side (transposed): [hi | lo | hi]
// ===========================================================================
__global__ void split_rows(const float* __restrict__ in, __nv_bfloat16* __restrict__ out,
                           int K) {
    int vi = blockIdx.x * blockDim.x + threadIdx.x;
    int kd4 = K >> 2;
    int m = vi / kd4;
    int kc = (vi % kd4) * 4;
    float4 v = *(const float4*)(in + (size_t)m * K + kc);
    __nv_bfloat16 h0 = __float2bfloat16(v.x), h1 = __float2bfloat16(v.y);
    __nv_bfloat16 h2 = __float2bfloat16(v.z), h3 = __float2bfloat16(v.w);
    __nv_bfloat16 l0 = __float2bfloat16(v.x - __bfloat162float(h0));
    __nv_bfloat16 l1 = __float2bfloat16(v.y - __bfloat162float(h1));
    __nv_bfloat16 l2 = __float2bfloat16(v.z - __bfloat162float(h2));
    __nv_bfloat16 l3 = __float2bfloat16(v.w - __bfloat162float(h3));
    __nv_bfloat162 h01; h01.x = h0; h01.y = h1;
    __nv_bfloat162 h23; h23.x = h2; h23.y = h3;
    __nv_bfloat162 l01; l01.x = l0; l01.y = l1;
    __nv_bfloat162 l23; l23.x = l2; l23.y = l3;
    uint2 hv = make_uint2(*(uint32_t*)&h01, *(uint32_t*)&h23);
    uint2 lv = make_uint2(*(uint32_t*)&l01, *(uint32_t*)&l23);
    __nv_bfloat16* o = out + (size_t)m * (3 * K);
    *(uint2*)(o + kc)         = hv;
    *(uint2*)(o + K + kc)     = hv;
    *(uint2*)(o + 2 * K + kc) = lv;
}

__global__ void split_transpose(const float* __restrict__ W, __nv_bfloat16* __restrict__ Bt,
                                int K, int N) {
    __shared__ float t[32][33];
    int n0 = blockIdx.x * 32, k0 = blockIdx.y * 32;
    int tx = threadIdx.x, ty = threadIdx.y;   // block (32, 8)
#pragma unroll
    for (int i = 0; i < 4; i++)
        t[ty + 8 * i][tx] = W[(size_t)(k0 + ty + 8 * i) * N + n0 + tx];
    __syncthreads();
#pragma unroll
    for (int i = 0; i < 4; i++) {
        int n = n0 + ty + 8 * i;
        int k = k0 + tx;
        float v = t[tx][ty + 8 * i];
        __nv_bfloat16 h = __float2bfloat16(v);
        __nv_bfloat16 l = __float2bfloat16(v - __bfloat162float(h));
        __nv_bfloat16* o = Bt + (size_t)n * (3 * K);
        o[k]         = h;
        o[K + k]     = l;
        o[2 * K + k] = h;
    }
}

// ===========================================================================
// Warp-MMA GEMM: C[m][n] = sum_k A[m][k] * Bt[n][k]  (bf16 in, fp32 out)
// CTA tile 128x128, K-stage 32, 256 threads (8 warps: 4 over M x 2 over N),
// warp tile 32x64, mma.sync.m16n8k16, 3-stage cp.async pipeline.
// smem rows padded to 40 halves (80B) -> conflict-free ldmatrix + STS.
// ===========================================================================
#define GK 32                       // K elems per stage
#define AROW 40                     // padded row stride (halves)
#define ATILE_B (128 * AROW * 2)    // 10240 bytes per operand per stage
#define STAGE_B (2 * ATILE_B)       // 20480
#define NSTAGE 3
#define GEMM_SMEM (NSTAGE * STAGE_B)

__global__ __launch_bounds__(256, 1)
void gemm_mma(const __nv_bfloat16* __restrict__ A, const __nv_bfloat16* __restrict__ Bt,
              float* __restrict__ C, int Nc, int KK) {
    extern __shared__ __align__(128) char smbuf[];
    const uint32_t sbase = smem_u32(smbuf);

    const int tid  = threadIdx.x;
    const int wid  = tid >> 5;
    const int lane = tid & 31;
    const int m0 = blockIdx.y * 128;
    const int n0 = blockIdx.x * 128;
    const int wm = wid & 3;          // 0..3 -> 32-row slice
    const int wn = wid >> 2;         // 0..1 -> 64-col slice

    float acc[2][8][4];
#pragma unroll
    for (int i = 0; i < 2; i++)
#pragma unroll
        for (int j = 0; j < 8; j++)
#pragma unroll
            for (int l = 0; l < 4; l++) acc[i][j][l] = 0.f;

    // gmem->smem mapping: thread handles one row (t>>1) and two 16B chunks
    const int lrow = tid >> 1;
    const int lc   = (tid & 1) * 2;   // chunk index 0 or 2

    const int niter = KK / GK;        // 96

#define SM_A(st) (sbase + (st) * STAGE_B)
#define SM_B(st) (sbase + (st) * STAGE_B + ATILE_B)

#define LOAD_STAGE(st, it) do {                                               \
    const __nv_bfloat16* ga = A + (size_t)(m0 + lrow) * KK + (size_t)(it) * GK + lc * 8; \
    const __nv_bfloat16* gb = Bt + (size_t)(n0 + lrow) * KK + (size_t)(it) * GK + lc * 8; \
    uint32_t sa = SM_A(st) + lrow * (AROW * 2) + lc * 16;                     \
    uint32_t sb = SM_B(st) + lrow * (AROW * 2) + lc * 16;                     \
    cpasync16(sa, ga); cpasync16(sa + 16, ga + 8);                            \
    cpasync16(sb, gb); cpasync16(sb + 16, gb + 8);                            \
    CP_COMMIT();                                                              \
} while (0)

    LOAD_STAGE(0, 0);
    LOAD_STAGE(1, 1);

    // ldmatrix lane->address components (constant across iters)
    const int a_r16 = lane & 15;               // row within 16
    const int a_hi  = (lane & 16) ? 16 : 0;    // +16B for k8..15 matrices
    const int b_r   = (lane & 7) + ((lane & 16) ? 8 : 0);
    const int b_hi  = (lane & 8) ? 16 : 0;

    for (int it = 0; it < niter; it++) {
        const int st = it % NSTAGE;
        CP_WAIT1();
        __syncthreads();

        const uint32_t ab = SM_A(st);
        const uint32_t bb = SM_B(st);
#pragma unroll
        for (int s = 0; s < 2; s++) {           // two k16 steps
            uint32_t a0[4], a1[4];
            ldsm4(a0, ab + (wm * 32 + a_r16) * (AROW * 2) + s * 32 + a_hi);
            ldsm4(a1, ab + (wm * 32 + 16 + a_r16) * (AROW * 2) + s * 32 + a_hi);
            uint32_t bf[8][2];
#pragma unroll
            for (int g = 0; g < 4; g++) {
                uint32_t r[4];
                ldsm4(r, bb + (wn * 64 + g * 16 + b_r) * (AROW * 2) + s * 32 + b_hi);
                bf[2 * g][0] = r[0]; bf[2 * g][1] = r[1];
                bf[2 * g + 1][0] = r[2]; bf[2 * g + 1][1] = r[3];
            }
#pragma unroll
            for (int nt = 0; nt < 8; nt++) {
                mma16816(acc[0][nt], a0, bf[nt]);
                mma16816(acc[1][nt], a1, bf[nt]);
            }
        }
        __syncthreads();

        if (it + 2 < niter) LOAD_STAGE((it + 2) % NSTAGE, it + 2);
        else CP_COMMIT();   // keep group count consistent for CP_WAIT1
    }

    // Epilogue: direct global stores
    const int g4 = lane >> 2;       // row group 0..7
    const int q4 = lane & 3;        // col quad
#pragma unroll
    for (int mt = 0; mt < 2; mt++) {
        int r0 = m0 + wm * 32 + mt * 16 + g4;
#pragma unroll
        for (int nt = 0; nt < 8; nt++) {
            int cc = n0 + wn * 64 + nt * 8 + q4 * 2;
            *(float2*)(C + (size_t)r0 * Nc + cc) =
                make_float2(acc[mt][nt][0], acc[mt][nt][1]);
            *(float2*)(C + (size_t)(r0 + 8) * Nc + cc) =
                make_float2(acc[mt][nt][2], acc[mt][nt][3]);
        }
    }
#undef LOAD_STAGE
#undef SM_A
#undef SM_B
}

// ===========================================================================
// Flash attention (causal), fp32 — unchanged (validated in R2)
// ===========================================================================
#define AT_STRIDE 68
#define AT_TILE   (64 * AT_STRIDE)
#define AT_SMEM_FLOATS (3 * AT_TILE + 128)
#define AT_SMEM_BYTES  (AT_SMEM_FLOATS * 4)

__global__ __launch_bounds__(256)
void attn_kernel(const float* __restrict__ qkv, float* __restrict__ out) {
    extern __shared__ float smf[];
    float* Qs      = smf;
    float* KVs     = Qs + AT_TILE;
    float* Ss      = KVs + AT_TILE;
    float* alpha_s = Ss + AT_TILE;
    float* linv_s  = alpha_s + 64;

    const int tid = threadIdx.x;
    const int tx = tid & 15;
    const int ty = tid >> 4;
    const int qb = blockIdx.x;
    const int h  = blockIdx.y;
    const int b  = blockIdx.z;
    const int q0 = qb * 64;

    const float* base = qkv + (size_t)b * SEQ * N3;
    const int qoff = h * HDIM;
    const int koff = DMODEL + h * HDIM;
    const int voff = 2 * DMODEL + h * HDIM;

#pragma unroll
    for (int l = 0; l < 4; l++) {
        int idx = tid + l * 256;
        int row = idx >> 4;
        int dq  = (idx & 15) * 4;
        float4 v = *(const float4*)(base + (size_t)(q0 + row) * N3 + qoff + dq);
        Qs[(dq + 0) * AT_STRIDE + row] = v.x;
        Qs[(dq + 1) * AT_STRIDE + row] = v.y;
        Qs[(dq + 2) * AT_STRIDE + row] = v.z;
        Qs[(dq + 3) * AT_STRIDE + row] = v.w;
    }

    float O[4][4];
#pragma unroll
    for (int i = 0; i < 4; i++)
#pragma unroll
        for (int j = 0; j < 4; j++) O[i][j] = 0.f;

    const int srow = tid >> 2;
    const int sseg = tid & 3;
    float m_r = -1e30f, l_r = 0.f;

    for (int jt = 0; jt <= qb; jt++) {
        const int k0 = jt * 64;
#pragma unroll
        for (int l = 0; l < 4; l++) {
            int idx = tid + l * 256;
            int row = idx >> 4;
            int dq  = (idx & 15) * 4;
            float4 v = *(const float4*)(base + (size_t)(k0 + row) * N3 + koff + dq);
            KVs[(dq + 0) * AT_STRIDE + row] = v.x;
            KVs[(dq + 1) * AT_STRIDE + row] = v.y;
            KVs[(dq + 2) * AT_STRIDE + row] = v.z;
            KVs[(dq + 3) * AT_STRIDE + row] = v.w;
        }
        __syncthreads();

        float s[4][4];
#pragma unroll
        for (int i = 0; i < 4; i++)
#pragma unroll
            for (int j = 0; j < 4; j++) s[i][j] = 0.f;

#pragma unroll
        for (int kk = 0; kk < 64; kk++) {
            float4 a = *(float4*)&Qs[kk * AT_STRIDE + ty * 4];
            float4 bb = *(float4*)&KVs[kk * AT_STRIDE + tx * 4];
            s[0][0] = fmaf(a.x, bb.x, s[0][0]); s[0][1] = fmaf(a.x, bb.y, s[0][1]);
            s[0][2] = fmaf(a.x, bb.z, s[0][2]); s[0][3] = fmaf(a.x, bb.w, s[0][3]);
            s[1][0] = fmaf(a.y, bb.x, s[1][0]); s[1][1] = fmaf(a.y, bb.y, s[1][1]);
            s[1][2] = fmaf(a.y, bb.z, s[1][2]); s[1][3] = fmaf(a.y, bb.w, s[1][3]);
            s[2][0] = fmaf(a.z, bb.x, s[2][0]); s[2][1] = fmaf(a.z, bb.y, s[2][1]);
            s[2][2] = fmaf(a.z, bb.z, s[2][2]); s[2][3] = fmaf(a.z, bb.w, s[2][3]);
            s[3][0] = fmaf(a.w, bb.x, s[3][0]); s[3][1] = fmaf(a.w, bb.y, s[3][1]);
            s[3][2] = fmaf(a.w, bb.z, s[3][2]); s[3][3] = fmaf(a.w, bb.w, s[3][3]);
        }

        const bool diag = (jt == qb);
#pragma unroll
        for (int i = 0; i < 4; i++) {
            int q = ty * 4 + i;
            float vv[4];
#pragma unroll
            for (int j = 0; j < 4; j++) {
                float val = s[i][j] * 0.125f;
                if (diag && (tx * 4 + j) > q) val = -1e30f;
                vv[j] = val;
            }
            *(float4*)&Ss[q * AT_STRIDE + tx * 4] = make_float4(vv[0], vv[1], vv[2], vv[3]);
        }
        __syncthreads();

        {
            const int jb = sseg * 16;
            float mloc = -1e30f;
#pragma unroll
            for (int j = 0; j < 16; j++)
                mloc = fmaxf(mloc, Ss[srow * AT_STRIDE + jb + j]);
            mloc = fmaxf(mloc, __shfl_xor_sync(0xffffffffu, mloc, 1));
            mloc = fmaxf(mloc, __shfl_xor_sync(0xffffffffu, mloc, 2));
            float mn = fmaxf(m_r, mloc);
            float al = __expf(m_r - mn);
            float ls = 0.f;
#pragma unroll
            for (int j = 0; j < 16; j++) {
                float p = __expf(Ss[srow * AT_STRIDE + jb + j] - mn);
                Ss[srow * AT_STRIDE + jb + j] = p;
                ls += p;
            }
            ls += __shfl_xor_sync(0xffffffffu, ls, 1);
            ls += __shfl_xor_sync(0xffffffffu, ls, 2);
            l_r = l_r * al + ls;
            m_r = mn;
            if (sseg == 0) alpha_s[srow] = al;
        }
        __syncthreads();

#pragma unroll
        for (int i = 0; i < 4; i++) {
            float al = alpha_s[ty * 4 + i];
#pragma unroll
            for (int j = 0; j < 4; j++) O[i][j] *= al;
        }

#pragma unroll
        for (int l = 0; l < 4; l++) {
            int idx = tid + l * 256;
            int row = idx >> 4;
            int dq  = (idx & 15) * 4;
            float4 v = *(const float4*)(base + (size_t)(k0 + row) * N3 + voff + dq);
            *(float4*)&KVs[row * AT_STRIDE + dq] = v;
        }
        __syncthreads();

#pragma unroll
        for (int kk = 0; kk < 64; kk += 4) {
            float4 a0 = *(float4*)&Ss[(ty * 4 + 0) * AT_STRIDE + kk];
            float4 a1 = *(float4*)&Ss[(ty * 4 + 1) * AT_STRIDE + kk];
            float4 a2 = *(float4*)&Ss[(ty * 4 + 2) * AT_STRIDE + kk];
            float4 a3 = *(float4*)&Ss[(ty * 4 + 3) * AT_STRIDE + kk];
            float4 b0 = *(float4*)&KVs[(kk + 0) * AT_STRIDE + tx * 4];
            float4 b1 = *(float4*)&KVs[(kk + 1) * AT_STRIDE + tx * 4];
            float4 b2 = *(float4*)&KVs[(kk + 2) * AT_STRIDE + tx * 4];
            float4 b3 = *(float4*)&KVs[(kk + 3) * AT_STRIDE + tx * 4];
#define ACC_ROW(i, av)                                              \
            O[i][0] = fmaf(av.x, b0.x, O[i][0]);                    \
            O[i][1] = fmaf(av.x, b0.y, O[i][1]);                    \
            O[i][2] = fmaf(av.x, b0.z, O[i][2]);                    \
            O[i][3] = fmaf(av.x, b0.w, O[i][3]);                    \
            O[i][0] = fmaf(av.y, b1.x, O[i][0]);                    \
            O[i][1] = fmaf(av.y, b1.y, O[i][1]);                    \
            O[i][2] = fmaf(av.y, b1.z, O[i][2]);                    \
            O[i][3] = fmaf(av.y, b1.w, O[i][3]);                    \
            O[i][0] = fmaf(av.z, b2.x, O[i][0]);                    \
            O[i][1] = fmaf(av.z, b2.y, O[i][1]);                    \
            O[i][2] = fmaf(av.z, b2.z, O[i][2]);                    \
            O[i][3] = fmaf(av.z, b2.w, O[i][3]);                    \
            O[i][0] = fmaf(av.w, b3.x, O[i][0]);                    \
            O[i][1] = fmaf(av.w, b3.y, O[i][1]);                    \
            O[i][2] = fmaf(av.w, b3.z, O[i][2]);                    \
            O[i][3] = fmaf(av.w, b3.w, O[i][3]);
            ACC_ROW(0, a0)
            ACC_ROW(1, a1)
            ACC_ROW(2, a2)
            ACC_ROW(3, a3)
#undef ACC_ROW
        }
        __syncthreads();
    }

    if (sseg == 0) linv_s[srow] = 1.f / l_r;
    __syncthreads();

    float* outp = out + ((size_t)b * SEQ + q0) * DMODEL + h * HDIM;
#pragma unroll
    for (int i = 0; i < 4; i++) {
        float inv = linv_s[ty * 4 + i];
        float4 v = make_float4(O[i][0] * inv, O[i][1] * inv,
                               O[i][2] * inv, O[i][3] * inv);
        *(float4*)(outp + (size_t)(ty * 4 + i) * DMODEL + tx * 4) = v;
    }
}

// ===========================================================================
// Launch
// ===========================================================================
extern "C" void kernel_launch(void* const* d_in, const int* in_sizes, int n_in,
                              void* d_out, int out_size) {
    const float* x    = (const float*)d_in[0];
    // d_in[1] = mask (tril) — causality applied analytically
    const float* Wqkv = (const float*)d_in[2];
    const float* Wout = (const float*)d_in[3];
    float* out = (float*)d_out;

    float *qkv, *attn;
    __nv_bfloat16 *a3, *btq, *bto;
    cudaGetSymbolAddress((void**)&qkv, g_qkv);
    cudaGetSymbolAddress((void**)&attn, g_attn);
    cudaGetSymbolAddress((void**)&a3, g_a3);
    cudaGetSymbolAddress((void**)&btq, g_btq);
    cudaGetSymbolAddress((void**)&bto, g_bto);

    cudaFuncSetAttribute(gemm_mma, cudaFuncAttributeMaxDynamicSharedMemorySize, GEMM_SMEM);
    cudaFuncSetAttribute(attn_kernel, cudaFuncAttributeMaxDynamicSharedMemorySize,
                         AT_SMEM_BYTES);

    // 1. Split inputs
    split_rows<<<(ROWS * DMODEL / 4) / 256, 256>>>(x, a3, DMODEL);
    split_transpose<<<dim3(N3 / 32, DMODEL / 32), dim3(32, 8)>>>(Wqkv, btq, DMODEL, N3);

    // 2. QKV projection on tensor cores (HMMA)
    gemm_mma<<<dim3(N3 / 128, ROWS / 128), 256, GEMM_SMEM>>>(a3, btq, qkv, N3, KK3);

    // 3. Causal flash attention (fp32)
    attn_kernel<<<dim3(SEQ / 64, NHEADS, BATCH), 256, AT_SMEM_BYTES>>>(qkv, attn);

    // 4. Split attention output + Wout
    split_rows<<<(ROWS * DMODEL / 4) / 256, 256>>>(attn, a3, DMODEL);
    split_transpose<<<dim3(DMODEL / 32, DMODEL / 32), dim3(32, 8)>>>(Wout, bto, DMODEL, DMODEL);

    // 5. Output projection on tensor cores
    gemm_mma<<<dim3(DMODEL / 128, ROWS / 128), 256, GEMM_SMEM>>>(a3, bto, out, DMODEL, KK3);
}

// round 9
// speedup vs baseline: 2.0218x; 1.7319x over previous
#include <cuda_runtime.h>
#include <cuda_bf16.h>
#include <cuda_fp16.h>
#include <cstdint>
#include <math.h>

// Problem constants
#define BATCH 2
#define SEQ 2048
#define DMODEL 1024
#define NHEADS 16
#define HDIM 64
#define N3 (3 * DMODEL)
#define ROWS (BATCH * SEQ)   // 4096
#define KK3 (3 * DMODEL)     // split K' = 3072

// Scratch
__device__ __half g_qkv[(size_t)ROWS * N3];           // [4096, 3072] fp16 (QKV proj out)
__device__ float g_attn[(size_t)ROWS * DMODEL];       // [4096, 1024] fp32
__device__ __nv_bfloat16 g_a3[(size_t)ROWS * KK3];    // split A: [4096, 3072]
__device__ __nv_bfloat16 g_btq[(size_t)N3 * KK3];     // split-T Wqkv: [3072, 3072]
__device__ __nv_bfloat16 g_bto[(size_t)DMODEL * KK3]; // split-T Wout: [1024, 3072]

// ===========================================================================
// Helpers (sm_80-level PTX only — target is plain compute_103)
// ===========================================================================
__device__ __forceinline__ uint32_t smem_u32(const void* p) {
    uint32_t a;
    asm("{ .reg .u64 t; cvta.to.shared.u64 t, %1; cvt.u32.u64 %0, t; }"
        : "=r"(a) : "l"(p));
    return a;
}
__device__ __forceinline__ void cpasync16(uint32_t saddr, const void* gaddr) {
    asm volatile("cp.async.cg.shared.global [%0], [%1], 16;"
                 :: "r"(saddr), "l"(gaddr));
}
#define CP_COMMIT() asm volatile("cp.async.commit_group;" ::: "memory")
#define CP_WAIT1()  asm volatile("cp.async.wait_group 1;" ::: "memory")

__device__ __forceinline__ void ldsm4(uint32_t* r, uint32_t addr) {
    asm volatile("ldmatrix.sync.aligned.m8n8.x4.shared.b16 {%0,%1,%2,%3}, [%4];"
                 : "=r"(r[0]), "=r"(r[1]), "=r"(r[2]), "=r"(r[3]) : "r"(addr));
}
__device__ __forceinline__ void ldsm4t(uint32_t* r, uint32_t addr) {
    asm volatile("ldmatrix.sync.aligned.m8n8.x4.trans.shared.b16 {%0,%1,%2,%3}, [%4];"
                 : "=r"(r[0]), "=r"(r[1]), "=r"(r[2]), "=r"(r[3]) : "r"(addr));
}
// bf16 MMA (projections)
__device__ __forceinline__ void mma16816(float* c, const uint32_t* a, const uint32_t* b) {
    asm volatile(
        "mma.sync.aligned.m16n8k16.row.col.f32.bf16.bf16.f32 "
        "{%0,%1,%2,%3}, {%4,%5,%6,%7}, {%8,%9}, {%0,%1,%2,%3};"
        : "+f"(c[0]), "+f"(c[1]), "+f"(c[2]), "+f"(c[3])
        : "r"(a[0]), "r"(a[1]), "r"(a[2]), "r"(a[3]), "r"(b[0]), "r"(b[1]));
}
// fp16 MMA (attention)
__device__ __forceinline__ void mma16816h(float* c, const uint32_t* a, const uint32_t* b) {
    asm volatile(
        "mma.sync.aligned.m16n8k16.row.col.f32.f16.f16.f32 "
        "{%0,%1,%2,%3}, {%4,%5,%6,%7}, {%8,%9}, {%0,%1,%2,%3};"
        : "+f"(c[0]), "+f"(c[1]), "+f"(c[2]), "+f"(c[3])
        : "r"(a[0]), "r"(a[1]), "r"(a[2]), "r"(a[3]), "r"(b[0]), "r"(b[1]));
}

// ===========================================================================
// Split kernels: fp32 -> bf16 hi/lo, 3-term layout
// A side: [hi | hi | lo], B side (transposed): [hi | lo | hi]
// ===========================================================================
__global__ void split_rows(const float* __restrict__ in, __nv_bfloat16* __restrict__ out,
                           int K) {
    int vi = blockIdx.x * blockDim.x + threadIdx.x;
    int kd4 = K >> 2;
    int m = vi / kd4;
    int kc = (vi % kd4) * 4;
    float4 v = *(const float4*)(in + (size_t)m * K + kc);
    __nv_bfloat16 h0 = __float2bfloat16(v.x), h1 = __float2bfloat16(v.y);
    __nv_bfloat16 h2 = __float2bfloat16(v.z), h3 = __float2bfloat16(v.w);
    __nv_bfloat16 l0 = __float2bfloat16(v.x - __bfloat162float(h0));
    __nv_bfloat16 l1 = __float2bfloat16(v.y - __bfloat162float(h1));
    __nv_bfloat16 l2 = __float2bfloat16(v.z - __bfloat162float(h2));
    __nv_bfloat16 l3 = __float2bfloat16(v.w - __bfloat162float(h3));
    __nv_bfloat162 h01; h01.x = h0; h01.y = h1;
    __nv_bfloat162 h23; h23.x = h2; h23.y = h3;
    __nv_bfloat162 l01; l01.x = l0; l01.y = l1;
    __nv_bfloat162 l23; l23.x = l2; l23.y = l3;
    uint2 hv = make_uint2(*(uint32_t*)&h01, *(uint32_t*)&h23);
    uint2 lv = make_uint2(*(uint32_t*)&l01, *(uint32_t*)&l23);
    __nv_bfloat16* o = out + (size_t)m * (3 * K);
    *(uint2*)(o + kc)         = hv;
    *(uint2*)(o + K + kc)     = hv;
    *(uint2*)(o + 2 * K + kc) = lv;
}

__global__ void split_transpose(const float* __restrict__ W, __nv_bfloat16* __restrict__ Bt,
                                int K, int N) {
    __shared__ float t[32][33];
    int n0 = blockIdx.x * 32, k0 = blockIdx.y * 32;
    int tx = threadIdx.x, ty = threadIdx.y;   // block (32, 8)
#pragma unroll
    for (int i = 0; i < 4; i++)
        t[ty + 8 * i][tx] = W[(size_t)(k0 + ty + 8 * i) * N + n0 + tx];
    __syncthreads();
#pragma unroll
    for (int i = 0; i < 4; i++) {
        int n = n0 + ty + 8 * i;
        int k = k0 + tx;
        float v = t[tx][ty + 8 * i];
        __nv_bfloat16 h = __float2bfloat16(v);
        __nv_bfloat16 l = __float2bfloat16(v - __bfloat162float(h));
        __nv_bfloat16* o = Bt + (size_t)n * (3 * K);
        o[k]         = h;
        o[K + k]     = l;
        o[2 * K + k] = h;
    }
}

// ===========================================================================
// Warp-MMA GEMM (verified): C = A @ Bt^T, bf16 in, fp32 or fp16 out.
// ===========================================================================
#define GK 32
#define AROW 40
#define ATILE_B (128 * AROW * 2)
#define STAGE_B (2 * ATILE_B)
#define NSTAGE 3
#define GEMM_SMEM (NSTAGE * STAGE_B)

template <bool HALFOUT>
__global__ __launch_bounds__(256, 1)
void gemm_mma(const __nv_bfloat16* __restrict__ A, const __nv_bfloat16* __restrict__ Bt,
              void* __restrict__ Cv, int Nc, int KK) {
    extern __shared__ __align__(128) char smbuf[];
    const uint32_t sbase = smem_u32(smbuf);

    const int tid  = threadIdx.x;
    const int wid  = tid >> 5;
    const int lane = tid & 31;
    const int m0 = blockIdx.y * 128;
    const int n0 = blockIdx.x * 128;
    const int wm = wid & 3;
    const int wn = wid >> 2;

    float acc[2][8][4];
#pragma unroll
    for (int i = 0; i < 2; i++)
#pragma unroll
        for (int j = 0; j < 8; j++)
#pragma unroll
            for (int l = 0; l < 4; l++) acc[i][j][l] = 0.f;

    const int lrow = tid >> 1;
    const int lc   = (tid & 1) * 2;
    const int niter = KK / GK;

#define SM_A(st) (sbase + (st) * STAGE_B)
#define SM_B(st) (sbase + (st) * STAGE_B + ATILE_B)
#define LOAD_STAGE(st, it) do {                                               \
    const __nv_bfloat16* ga = A + (size_t)(m0 + lrow) * KK + (size_t)(it) * GK + lc * 8; \
    const __nv_bfloat16* gb = Bt + (size_t)(n0 + lrow) * KK + (size_t)(it) * GK + lc * 8; \
    uint32_t sa = SM_A(st) + lrow * (AROW * 2) + lc * 16;                     \
    uint32_t sb = SM_B(st) + lrow * (AROW * 2) + lc * 16;                     \
    cpasync16(sa, ga); cpasync16(sa + 16, ga + 8);                            \
    cpasync16(sb, gb); cpasync16(sb + 16, gb + 8);                            \
    CP_COMMIT();                                                              \
} while (0)

    LOAD_STAGE(0, 0);
    LOAD_STAGE(1, 1);

    const int a_r16 = lane & 15;
    const int a_hi  = (lane & 16) ? 16 : 0;
    const int b_r   = (lane & 7) + ((lane & 16) ? 8 : 0);
    const int b_hi  = (lane & 8) ? 16 : 0;

    for (int it = 0; it < niter; it++) {
        const int st = it % NSTAGE;
        CP_WAIT1();
        __syncthreads();

        const uint32_t ab = SM_A(st);
        const uint32_t bb = SM_B(st);
#pragma unroll
        for (int s = 0; s < 2; s++) {
            uint32_t a0[4], a1[4];
            ldsm4(a0, ab + (wm * 32 + a_r16) * (AROW * 2) + s * 32 + a_hi);
            ldsm4(a1, ab + (wm * 32 + 16 + a_r16) * (AROW * 2) + s * 32 + a_hi);
            uint32_t bf[8][2];
#pragma unroll
            for (int g = 0; g < 4; g++) {
                uint32_t r[4];
                ldsm4(r, bb + (wn * 64 + g * 16 + b_r) * (AROW * 2) + s * 32 + b_hi);
                bf[2 * g][0] = r[0]; bf[2 * g][1] = r[1];
                bf[2 * g + 1][0] = r[2]; bf[2 * g + 1][1] = r[3];
            }
#pragma unroll
            for (int nt = 0; nt < 8; nt++) {
                mma16816(acc[0][nt], a0, bf[nt]);
                mma16816(acc[1][nt], a1, bf[nt]);
            }
        }
        __syncthreads();

        if (it + 2 < niter) LOAD_STAGE((it + 2) % NSTAGE, it + 2);
        else CP_COMMIT();
    }

    const int g4 = lane >> 2;
    const int q4 = lane & 3;
#pragma unroll
    for (int mt = 0; mt < 2; mt++) {
        int r0 = m0 + wm * 32 + mt * 16 + g4;
#pragma unroll
        for (int nt = 0; nt < 8; nt++) {
            int cc = n0 + wn * 64 + nt * 8 + q4 * 2;
            if (HALFOUT) {
                __half* Cb = (__half*)Cv;
                __half2 p0 = __floats2half2_rn(acc[mt][nt][0], acc[mt][nt][1]);
                __half2 p1 = __floats2half2_rn(acc[mt][nt][2], acc[mt][nt][3]);
                *(uint32_t*)(Cb + (size_t)r0 * Nc + cc) = *(uint32_t*)&p0;
                *(uint32_t*)(Cb + (size_t)(r0 + 8) * Nc + cc) = *(uint32_t*)&p1;
            } else {
                float* Cf = (float*)Cv;
                *(float2*)(Cf + (size_t)r0 * Nc + cc) =
                    make_float2(acc[mt][nt][0], acc[mt][nt][1]);
                *(float2*)(Cf + (size_t)(r0 + 8) * Nc + cc) =
                    make_float2(acc[mt][nt][2], acc[mt][nt][3]);
            }
        }
    }
#undef LOAD_STAGE
#undef SM_A
#undef SM_B
}

// ===========================================================================
// Tensor-core flash attention (causal), fp16 MMA + fp32 softmax.
// Grid (SEQ/64, NHEADS, BATCH), 256 threads (8 warps: 4 over q x 2 over k/d).
// qkv is fp16 [row][3072]. out fp32 [row][1024].
// ===========================================================================
#define ASTR 72                         // smem row stride in halves (144 B)
#define ATILE_BYTES (64 * ASTR * 2)     // 9216
#define OFF_Q  0
#define OFF_K  ATILE_BYTES
#define OFF_V  (2 * ATILE_BYTES)
#define OFF_P  (3 * ATILE_BYTES)
#define OFF_MX (4 * ATILE_BYTES)             // float[64][2]
#define OFF_SU (OFF_MX + 512)                // float[64][2]
#define OFF_M  (OFF_SU + 512)                // float[64]
#define OFF_L  (OFF_M + 256)                 // float[64]
#define OFF_AL (OFF_L + 256)                 // float[64]
#define ATT_SMEM (OFF_AL + 256)

__global__ __launch_bounds__(256)
void attn_mma(const __half* __restrict__ qkv, float* __restrict__ out) {
    extern __shared__ __align__(128) char sm[];
    const uint32_t sb = smem_u32(sm);
    float* mx_s = (float*)(sm + OFF_MX);
    float* su_s = (float*)(sm + OFF_SU);
    float* m_s  = (float*)(sm + OFF_M);
    float* l_s  = (float*)(sm + OFF_L);
    float* al_s = (float*)(sm + OFF_AL);

    const int tid  = threadIdx.x;
    const int wid  = tid >> 5;
    const int lane = tid & 31;
    const int wq = wid & 3;        // q-slice (16 rows)
    const int wk = wid >> 2;       // k/d-slice (32 cols)
    const int g4 = lane >> 2;
    const int q4 = lane & 3;
    const int qb = blockIdx.x;
    const int h  = blockIdx.y;
    const int b  = blockIdx.z;
    const int q0 = qb * 64;

    const __half* base = qkv + (size_t)b * SEQ * N3;
    const __half* qp = base + (size_t)q0 * N3 + h * HDIM;

    // ldmatrix lane addressing constants
    const int a_r16 = lane & 15;
    const int a_hi  = (lane & 16) ? 16 : 0;
    const int b_r   = (lane & 7) + ((lane & 16) ? 8 : 0);
    const int b_hi  = (lane & 8) ? 16 : 0;
    const int v_r   = (lane & 7) + ((lane & 8) ? 8 : 0);
    const int v_c   = (lane & 16) ? 8 : 0;

    // Load Q tile (64 rows x 64 fp16) into smem
#pragma unroll
    for (int l = 0; l < 2; l++) {
        int idx = tid + l * 256;          // 0..511
        int row = idx >> 3;
        int dc  = (idx & 7) * 8;
        uint4 v = *(const uint4*)(qp + (size_t)row * N3 + dc);
        *(uint4*)(sm + OFF_Q + row * (ASTR * 2) + dc * 2) = v;
    }
    if (tid < 64) { m_s[tid] = -1e30f; l_s[tid] = 0.f; }

    float O[4][4];
#pragma unroll
    for (int i = 0; i < 4; i++)
#pragma unroll
        for (int j = 0; j < 4; j++) O[i][j] = 0.f;

    const int r1 = wq * 16 + g4;
    const int r2 = r1 + 8;

    __syncthreads();

    for (int jt = 0; jt <= qb; jt++) {
        const int k0 = jt * 64;
        const __half* kp = base + (size_t)k0 * N3 + DMODEL + h * HDIM;
        const __half* vp = base + (size_t)k0 * N3 + 2 * DMODEL + h * HDIM;

        // Load K, V tiles (fp16, 8 KB each)
#pragma unroll
        for (int l = 0; l < 2; l++) {
            int idx = tid + l * 256;
            int row = idx >> 3;
            int dc  = (idx & 7) * 8;
            uint4 kv = *(const uint4*)(kp + (size_t)row * N3 + dc);
            uint4 vv = *(const uint4*)(vp + (size_t)row * N3 + dc);
            *(uint4*)(sm + OFF_K + row * (ASTR * 2) + dc * 2) = kv;
            *(uint4*)(sm + OFF_V + row * (ASTR * 2) + dc * 2) = vv;
        }
        __syncthreads();

        // ---- S = Q @ K^T (contraction over d=64, 4 k16 steps) ----
        float sa[4][4];
#pragma unroll
        for (int nt = 0; nt < 4; nt++)
#pragma unroll
            for (int j = 0; j < 4; j++) sa[nt][j] = 0.f;

#pragma unroll
        for (int s = 0; s < 4; s++) {
            uint32_t af[4];
            ldsm4(af, sb + OFF_Q + (wq * 16 + a_r16) * (ASTR * 2) + s * 32 + a_hi);
            uint32_t bf[4][2];
#pragma unroll
            for (int g = 0; g < 2; g++) {
                uint32_t r[4];
                ldsm4(r, sb + OFF_K + (wk * 32 + g * 16 + b_r) * (ASTR * 2) + s * 32 + b_hi);
                bf[2 * g][0] = r[0]; bf[2 * g][1] = r[1];
                bf[2 * g + 1][0] = r[2]; bf[2 * g + 1][1] = r[3];
            }
#pragma unroll
            for (int nt = 0; nt < 4; nt++)
                mma16816h(sa[nt], af, bf[nt]);
        }

        // Scale + causal mask
        const bool diag = (jt == qb);
#pragma unroll
        for (int nt = 0; nt < 4; nt++) {
            int c = wk * 32 + nt * 8 + q4 * 2;
            sa[nt][0] *= 0.125f; sa[nt][1] *= 0.125f;
            sa[nt][2] *= 0.125f; sa[nt][3] *= 0.125f;
            if (diag) {
                if (c > r1)     sa[nt][0] = -1e30f;
                if (c + 1 > r1) sa[nt][1] = -1e30f;
                if (c > r2)     sa[nt][2] = -1e30f;
                if (c + 1 > r2) sa[nt][3] = -1e30f;
            }
        }

        // Row max over this warp's 32 cols
        float mx1 = -1e30f, mx2 = -1e30f;
#pragma unroll
        for (int nt = 0; nt < 4; nt++) {
            mx1 = fmaxf(mx1, fmaxf(sa[nt][0], sa[nt][1]));
            mx2 = fmaxf(mx2, fmaxf(sa[nt][2], sa[nt][3]));
        }
        mx1 = fmaxf(mx1, __shfl_xor_sync(0xffffffffu, mx1, 1));
        mx1 = fmaxf(mx1, __shfl_xor_sync(0xffffffffu, mx1, 2));
        mx2 = fmaxf(mx2, __shfl_xor_sync(0xffffffffu, mx2, 1));
        mx2 = fmaxf(mx2, __shfl_xor_sync(0xffffffffu, mx2, 2));
        if (q4 == 0) {
            mx_s[r1 * 2 + wk] = mx1;
            mx_s[r2 * 2 + wk] = mx2;
        }
        __syncthreads();

        if (tid < 64) {
            float mo = m_s[tid];
            float mn = fmaxf(mo, fmaxf(mx_s[tid * 2], mx_s[tid * 2 + 1]));
            m_s[tid]  = mn;
            al_s[tid] = __expf(mo - mn);
        }
        __syncthreads();

        // p = exp(s - m); write P fp16; row partial sums; rescale O
        const float m1 = m_s[r1], m2 = m_s[r2];
        float s1 = 0.f, s2 = 0.f;
#pragma unroll
        for (int nt = 0; nt < 4; nt++) {
            int c = wk * 32 + nt * 8 + q4 * 2;
            float p0 = __expf(sa[nt][0] - m1);
            float p1 = __expf(sa[nt][1] - m1);
            float p2 = __expf(sa[nt][2] - m2);
            float p3 = __expf(sa[nt][3] - m2);
            s1 += p0 + p1;
            s2 += p2 + p3;
            __half2 h1 = __floats2half2_rn(p0, p1);
            __half2 h2 = __floats2half2_rn(p2, p3);
            *(uint32_t*)(sm + OFF_P + r1 * (ASTR * 2) + c * 2) = *(uint32_t*)&h1;
            *(uint32_t*)(sm + OFF_P + r2 * (ASTR * 2) + c * 2) = *(uint32_t*)&h2;
        }
        s1 += __shfl_xor_sync(0xffffffffu, s1, 1);
        s1 += __shfl_xor_sync(0xffffffffu, s1, 2);
        s2 += __shfl_xor_sync(0xffffffffu, s2, 1);
        s2 += __shfl_xor_sync(0xffffffffu, s2, 2);
        if (q4 == 0) {
            su_s[r1 * 2 + wk] = s1;
            su_s[r2 * 2 + wk] = s2;
        }
        {
            const float a1 = al_s[r1], a2 = al_s[r2];
#pragma unroll
            for (int nt = 0; nt < 4; nt++) {
                O[nt][0] *= a1; O[nt][1] *= a1;
                O[nt][2] *= a2; O[nt][3] *= a2;
            }
        }
        __syncthreads();

        if (tid < 64)
            l_s[tid] = l_s[tid] * al_s[tid] + su_s[tid * 2] + su_s[tid * 2 + 1];

        // ---- O += P @ V (contraction over 64 keys, 4 k16 steps) ----
#pragma unroll
        for (int s = 0; s < 4; s++) {
            uint32_t af[4];
            ldsm4(af, sb + OFF_P + (wq * 16 + a_r16) * (ASTR * 2) + s * 32 + a_hi);
            uint32_t bf[4][2];
#pragma unroll
            for (int g = 0; g < 2; g++) {
                uint32_t r[4];
                ldsm4t(r, sb + OFF_V + (s * 16 + v_r) * (ASTR * 2) +
                          (wk * 32 + g * 16 + v_c) * 2);
                bf[2 * g][0] = r[0]; bf[2 * g][1] = r[1];
                bf[2 * g + 1][0] = r[2]; bf[2 * g + 1][1] = r[3];
            }
#pragma unroll
            for (int nt = 0; nt < 4; nt++)
                mma16816h(O[nt], af, bf[nt]);
        }
        __syncthreads();
    }

    // Finalize
    const float li1 = 1.f / l_s[r1];
    const float li2 = 1.f / l_s[r2];
    float* op = out + ((size_t)b * SEQ + q0) * DMODEL + h * HDIM;
#pragma unroll
    for (int nt = 0; nt < 4; nt++) {
        int c = wk * 32 + nt * 8 + q4 * 2;
        *(float2*)(op + (size_t)r1 * DMODEL + c) =
            make_float2(O[nt][0] * li1, O[nt][1] * li1);
        *(float2*)(op + (size_t)r2 * DMODEL + c) =
            make_float2(O[nt][2] * li2, O[nt][3] * li2);
    }
}

// ===========================================================================
// Launch
// ===========================================================================
extern "C" void kernel_launch(void* const* d_in, const int* in_sizes, int n_in,
                              void* d_out, int out_size) {
    const float* x    = (const float*)d_in[0];
    // d_in[1] = mask (tril) — causality applied analytically
    const float* Wqkv = (const float*)d_in[2];
    const float* Wout = (const float*)d_in[3];
    float* out = (float*)d_out;

    float* attn;
    __half* qkv;
    __nv_bfloat16 *a3, *btq, *bto;
    cudaGetSymbolAddress((void**)&qkv, g_qkv);
    cudaGetSymbolAddress((void**)&attn, g_attn);
    cudaGetSymbolAddress((void**)&a3, g_a3);
    cudaGetSymbolAddress((void**)&btq, g_btq);
    cudaGetSymbolAddress((void**)&bto, g_bto);

    cudaFuncSetAttribute(gemm_mma<true>, cudaFuncAttributeMaxDynamicSharedMemorySize,
                         GEMM_SMEM);
    cudaFuncSetAttribute(gemm_mma<false>, cudaFuncAttributeMaxDynamicSharedMemorySize,
                         GEMM_SMEM);
    cudaFuncSetAttribute(attn_mma, cudaFuncAttributeMaxDynamicSharedMemorySize,
                         ATT_SMEM);

    // 1. Split inputs
    split_rows<<<(ROWS * DMODEL / 4) / 256, 256>>>(x, a3, DMODEL);
    split_transpose<<<dim3(N3 / 32, DMODEL / 32), dim3(32, 8)>>>(Wqkv, btq, DMODEL, N3);

    // 2. QKV projection (HMMA), fp16 output for attention
    gemm_mma<true><<<dim3(N3 / 128, ROWS / 128), 256, GEMM_SMEM>>>(a3, btq, qkv, N3, KK3);

    // 3. Causal flash attention on tensor cores (fp16)
    attn_mma<<<dim3(SEQ / 64, NHEADS, BATCH), 256, ATT_SMEM>>>(qkv, attn);

    // 4. Split attention output + Wout
    split_rows<<<(ROWS * DMODEL / 4) / 256, 256>>>(attn, a3, DMODEL);
    split_transpose<<<dim3(DMODEL / 32, DMODEL / 32), dim3(32, 8)>>>(Wout, bto, DMODEL, DMODEL);

    // 5. Output projection (HMMA), fp32 output
    gemm_mma<false><<<dim3(DMODEL / 128, ROWS / 128), 256, GEMM_SMEM>>>(a3, bto, out,
                                                                        DMODEL, KK3);
}

// round 12
// speedup vs baseline: 4.2391x; 2.0966x over previous
#include <cuda_runtime.h>
#include <cuda_bf16.h>
#include <cuda_fp16.h>
#include <cstdint>
#include <math.h>

// Problem constants
#define BATCH 2
#define SEQ 2048
#define DMODEL 1024
#define NHEADS 16
#define HDIM 64
#define N3 (3 * DMODEL)
#define ROWS (BATCH * SEQ)   // 4096

// Scratch (fp16 pipeline)
__device__ __half g_xh[(size_t)ROWS * DMODEL];        // x in fp16
__device__ __half g_qkv[(size_t)ROWS * N3];           // QKV proj out, fp16
__device__ __half g_attnh[(size_t)ROWS * DMODEL];     // attention out, fp16
__device__ __half g_wqkvT[(size_t)N3 * DMODEL];       // Wqkv^T fp16 [3072,1024]
__device__ __half g_woutT[(size_t)DMODEL * DMODEL];   // Wout^T fp16 [1024,1024]

// ===========================================================================
// Helpers (sm_80-level PTX only — target is plain compute_103)
// ===========================================================================
__device__ __forceinline__ uint32_t smem_u32(const void* p) {
    uint32_t a;
    asm("{ .reg .u64 t; cvta.to.shared.u64 t, %1; cvt.u32.u64 %0, t; }"
        : "=r"(a) : "l"(p));
    return a;
}
__device__ __forceinline__ void cpasync16(uint32_t saddr, const void* gaddr) {
    asm volatile("cp.async.cg.shared.global [%0], [%1], 16;"
                 :: "r"(saddr), "l"(gaddr));
}
#define CP_COMMIT() asm volatile("cp.async.commit_group;" ::: "memory")
#define CP_WAIT1()  asm volatile("cp.async.wait_group 1;" ::: "memory")

__device__ __forceinline__ void ldsm4(uint32_t* r, uint32_t addr) {
    asm volatile("ldmatrix.sync.aligned.m8n8.x4.shared.b16 {%0,%1,%2,%3}, [%4];"
                 : "=r"(r[0]), "=r"(r[1]), "=r"(r[2]), "=r"(r[3]) : "r"(addr));
}
__device__ __forceinline__ void ldsm4t(uint32_t* r, uint32_t addr) {
    asm volatile("ldmatrix.sync.aligned.m8n8.x4.trans.shared.b16 {%0,%1,%2,%3}, [%4];"
                 : "=r"(r[0]), "=r"(r[1]), "=r"(r[2]), "=r"(r[3]) : "r"(addr));
}
// fp16 MMA, fp32 accum
__device__ __forceinline__ void mma16816h(float* c, const uint32_t* a, const uint32_t* b) {
    asm volatile(
        "mma.sync.aligned.m16n8k16.row.col.f32.f16.f16.f32 "
        "{%0,%1,%2,%3}, {%4,%5,%6,%7}, {%8,%9}, {%0,%1,%2,%3};"
        : "+f"(c[0]), "+f"(c[1]), "+f"(c[2]), "+f"(c[3])
        : "r"(a[0]), "r"(a[1]), "r"(a[2]), "r"(a[3]), "r"(b[0]), "r"(b[1]));
}

// ===========================================================================
// Convert kernels
// ===========================================================================
// fp32 -> fp16 elementwise (vectorized: 4 floats -> 4 halves per thread)
__global__ void conv_h(const float* __restrict__ in, __half* __restrict__ out) {
    int vi = blockIdx.x * blockDim.x + threadIdx.x;
    float4 v = *(const float4*)(in + (size_t)vi * 4);
    __half2 h0 = __floats2half2_rn(v.x, v.y);
    __half2 h1 = __floats2half2_rn(v.z, v.w);
    uint2 u = make_uint2(*(uint32_t*)&h0, *(uint32_t*)&h1);
    *(uint2*)(out + (size_t)vi * 4) = u;
}

// W [K,N] fp32 -> Bt [N,K] fp16 (transpose + convert)
__global__ void transp_h(const float* __restrict__ W, __half* __restrict__ Bt,
                         int K, int N) {
    __shared__ float t[32][33];
    int n0 = blockIdx.x * 32, k0 = blockIdx.y * 32;
    int tx = threadIdx.x, ty = threadIdx.y;   // block (32, 8)
#pragma unroll
    for (int i = 0; i < 4; i++)
        t[ty + 8 * i][tx] = W[(size_t)(k0 + ty + 8 * i) * N + n0 + tx];
    __syncthreads();
#pragma unroll
    for (int i = 0; i < 4; i++) {
        int n = n0 + ty + 8 * i;
        int k = k0 + tx;
        Bt[(size_t)n * K + k] = __float2half(t[tx][ty + 8 * i]);
    }
}

// ===========================================================================
// Warp-MMA GEMM: C[m][n] = sum_k A[m][k] * Bt[n][k]  (fp16 in, fp32/fp16 out)
// CTA tile 128x128, K-stage 32, 256 threads, 3-stage cp.async pipeline.
// ===========================================================================
#define GK 32
#define AROW 40
#define ATILE_B (128 * AROW * 2)
#define STAGE_B (2 * ATILE_B)
#define NSTAGE 3
#define GEMM_SMEM (NSTAGE * STAGE_B)

template <bool HALFOUT>
__global__ __launch_bounds__(256, 1)
void gemm_mma(const __half* __restrict__ A, const __half* __restrict__ Bt,
              void* __restrict__ Cv, int Nc, int KK) {
    extern __shared__ __align__(128) char smbuf[];
    const uint32_t sbase = smem_u32(smbuf);

    const int tid  = threadIdx.x;
    const int wid  = tid >> 5;
    const int lane = tid & 31;
    const int m0 = blockIdx.y * 128;
    const int n0 = blockIdx.x * 128;
    const int wm = wid & 3;
    const int wn = wid >> 2;

    float acc[2][8][4];
#pragma unroll
    for (int i = 0; i < 2; i++)
#pragma unroll
        for (int j = 0; j < 8; j++)
#pragma unroll
            for (int l = 0; l < 4; l++) acc[i][j][l] = 0.f;

    const int lrow = tid >> 1;
    const int lc   = (tid & 1) * 2;
    const int niter = KK / GK;

#define SM_A(st) (sbase + (st) * STAGE_B)
#define SM_B(st) (sbase + (st) * STAGE_B + ATILE_B)
#define LOAD_STAGE(st, it) do {                                               \
    const __half* ga = A + (size_t)(m0 + lrow) * KK + (size_t)(it) * GK + lc * 8; \
    const __half* gb = Bt + (size_t)(n0 + lrow) * KK + (size_t)(it) * GK + lc * 8; \
    uint32_t sa = SM_A(st) + lrow * (AROW * 2) + lc * 16;                     \
    uint32_t sb = SM_B(st) + lrow * (AROW * 2) + lc * 16;                     \
    cpasync16(sa, ga); cpasync16(sa + 16, ga + 8);                            \
    cpasync16(sb, gb); cpasync16(sb + 16, gb + 8);                            \
    CP_COMMIT();                                                              \
} while (0)

    LOAD_STAGE(0, 0);
    LOAD_STAGE(1, 1);

    const int a_r16 = lane & 15;
    const int a_hi  = (lane & 16) ? 16 : 0;
    const int b_r   = (lane & 7) + ((lane & 16) ? 8 : 0);
    const int b_hi  = (lane & 8) ? 16 : 0;

    for (int it = 0; it < niter; it++) {
        const int st = it % NSTAGE;
        CP_WAIT1();
        __syncthreads();

        const uint32_t ab = SM_A(st);
        const uint32_t bb = SM_B(st);
#pragma unroll
        for (int s = 0; s < 2; s++) {
            uint32_t a0[4], a1[4];
            ldsm4(a0, ab + (wm * 32 + a_r16) * (AROW * 2) + s * 32 + a_hi);
            ldsm4(a1, ab + (wm * 32 + 16 + a_r16) * (AROW * 2) + s * 32 + a_hi);
            uint32_t bf[8][2];
#pragma unroll
            for (int g = 0; g < 4; g++) {
                uint32_t r[4];
                ldsm4(r, bb + (wn * 64 + g * 16 + b_r) * (AROW * 2) + s * 32 + b_hi);
                bf[2 * g][0] = r[0]; bf[2 * g][1] = r[1];
                bf[2 * g + 1][0] = r[2]; bf[2 * g + 1][1] = r[3];
            }
#pragma unroll
            for (int nt = 0; nt < 8; nt++) {
                mma16816h(acc[0][nt], a0, bf[nt]);
                mma16816h(acc[1][nt], a1, bf[nt]);
            }
        }
        __syncthreads();

        if (it + 2 < niter) LOAD_STAGE((it + 2) % NSTAGE, it + 2);
        else CP_COMMIT();
    }

    const int g4 = lane >> 2;
    const int q4 = lane & 3;
#pragma unroll
    for (int mt = 0; mt < 2; mt++) {
        int r0 = m0 + wm * 32 + mt * 16 + g4;
#pragma unroll
        for (int nt = 0; nt < 8; nt++) {
            int cc = n0 + wn * 64 + nt * 8 + q4 * 2;
            if (HALFOUT) {
                __half* Cb = (__half*)Cv;
                __half2 p0 = __floats2half2_rn(acc[mt][nt][0], acc[mt][nt][1]);
                __half2 p1 = __floats2half2_rn(acc[mt][nt][2], acc[mt][nt][3]);
                *(uint32_t*)(Cb + (size_t)r0 * Nc + cc) = *(uint32_t*)&p0;
                *(uint32_t*)(Cb + (size_t)(r0 + 8) * Nc + cc) = *(uint32_t*)&p1;
            } else {
                float* Cf = (float*)Cv;
                *(float2*)(Cf + (size_t)r0 * Nc + cc) =
                    make_float2(acc[mt][nt][0], acc[mt][nt][1]);
                *(float2*)(Cf + (size_t)(r0 + 8) * Nc + cc) =
                    make_float2(acc[mt][nt][2], acc[mt][nt][3]);
            }
        }
    }
#undef LOAD_STAGE
#undef SM_A
#undef SM_B
}

// ===========================================================================
// Tensor-core flash attention (causal), fp16 MMA + fp32 softmax, fp16 out.
// Grid (SEQ/64, NHEADS, BATCH), 256 threads (8 warps: 4 over q x 2 over k/d).
// ===========================================================================
#define ASTR 72                         // smem row stride in halves (144 B)
#define ATILE_BYTES (64 * ASTR * 2)     // 9216
#define OFF_Q  0
#define OFF_K  ATILE_BYTES
#define OFF_V  (2 * ATILE_BYTES)
#define OFF_P  (3 * ATILE_BYTES)
#define OFF_MX (4 * ATILE_BYTES)             // float[64][2]
#define OFF_SU (OFF_MX + 512)                // float[64][2]
#define OFF_M  (OFF_SU + 512)                // float[64]
#define OFF_L  (OFF_M + 256)                 // float[64]
#define OFF_AL (OFF_L + 256)                 // float[64]
#define ATT_SMEM (OFF_AL + 256)

__global__ __launch_bounds__(256)
void attn_mma(const __half* __restrict__ qkv, __half* __restrict__ out) {
    extern __shared__ __align__(128) char sm[];
    const uint32_t sb = smem_u32(sm);
    float* mx_s = (float*)(sm + OFF_MX);
    float* su_s = (float*)(sm + OFF_SU);
    float* m_s  = (float*)(sm + OFF_M);
    float* l_s  = (float*)(sm + OFF_L);
    float* al_s = (float*)(sm + OFF_AL);

    const int tid  = threadIdx.x;
    const int wid  = tid >> 5;
    const int lane = tid & 31;
    const int wq = wid & 3;        // q-slice (16 rows)
    const int wk = wid >> 2;       // k/d-slice (32 cols)
    const int g4 = lane >> 2;
    const int q4 = lane & 3;
    const int qb = blockIdx.x;
    const int h  = blockIdx.y;
    const int b  = blockIdx.z;
    const int q0 = qb * 64;

    const __half* base = qkv + (size_t)b * SEQ * N3;
    const __half* qp = base + (size_t)q0 * N3 + h * HDIM;

    // ldmatrix lane addressing constants
    const int a_r16 = lane & 15;
    const int a_hi  = (lane & 16) ? 16 : 0;
    const int b_r   = (lane & 7) + ((lane & 16) ? 8 : 0);
    const int b_hi  = (lane & 8) ? 16 : 0;
    const int v_r   = (lane & 7) + ((lane & 8) ? 8 : 0);
    const int v_c   = (lane & 16) ? 8 : 0;

    // Load Q tile (64 rows x 64 fp16)
#pragma unroll
    for (int l = 0; l < 2; l++) {
        int idx = tid + l * 256;
        int row = idx >> 3;
        int dc  = (idx & 7) * 8;
        uint4 v = *(const uint4*)(qp + (size_t)row * N3 + dc);
        *(uint4*)(sm + OFF_Q + row * (ASTR * 2) + dc * 2) = v;
    }
    if (tid < 64) { m_s[tid] = -1e30f; l_s[tid] = 0.f; }

    float O[4][4];
#pragma unroll
    for (int i = 0; i < 4; i++)
#pragma unroll
        for (int j = 0; j < 4; j++) O[i][j] = 0.f;

    const int r1 = wq * 16 + g4;
    const int r2 = r1 + 8;

    __syncthreads();

    for (int jt = 0; jt <= qb; jt++) {
        const int k0 = jt * 64;
        const __half* kp = base + (size_t)k0 * N3 + DMODEL + h * HDIM;
        const __half* vp = base + (size_t)k0 * N3 + 2 * DMODEL + h * HDIM;

        // Load K, V tiles (fp16, 8 KB each)
#pragma unroll
        for (int l = 0; l < 2; l++) {
            int idx = tid + l * 256;
            int row = idx >> 3;
            int dc  = (idx & 7) * 8;
            uint4 kv = *(const uint4*)(kp + (size_t)row * N3 + dc);
            uint4 vv = *(const uint4*)(vp + (size_t)row * N3 + dc);
            *(uint4*)(sm + OFF_K + row * (ASTR * 2) + dc * 2) = kv;
            *(uint4*)(sm + OFF_V + row * (ASTR * 2) + dc * 2) = vv;
        }
        __syncthreads();

        // ---- S = Q @ K^T ----
        float sa[4][4];
#pragma unroll
        for (int nt = 0; nt < 4; nt++)
#pragma unroll
            for (int j = 0; j < 4; j++) sa[nt][j] = 0.f;

#pragma unroll
        for (int s = 0; s < 4; s++) {
            uint32_t af[4];
            ldsm4(af, sb + OFF_Q + (wq * 16 + a_r16) * (ASTR * 2) + s * 32 + a_hi);
            uint32_t bf[4][2];
#pragma unroll
            for (int g = 0; g < 2; g++) {
                uint32_t r[4];
                ldsm4(r, sb + OFF_K + (wk * 32 + g * 16 + b_r) * (ASTR * 2) + s * 32 + b_hi);
                bf[2 * g][0] = r[0]; bf[2 * g][1] = r[1];
                bf[2 * g + 1][0] = r[2]; bf[2 * g + 1][1] = r[3];
            }
#pragma unroll
            for (int nt = 0; nt < 4; nt++)
                mma16816h(sa[nt], af, bf[nt]);
        }

        // Scale + causal mask
        const bool diag = (jt == qb);
#pragma unroll
        for (int nt = 0; nt < 4; nt++) {
            int c = wk * 32 + nt * 8 + q4 * 2;
            sa[nt][0] *= 0.125f; sa[nt][1] *= 0.125f;
            sa[nt][2] *= 0.125f; sa[nt][3] *= 0.125f;
            if (diag) {
                if (c > r1)     sa[nt][0] = -1e30f;
                if (c + 1 > r1) sa[nt][1] = -1e30f;
                if (c > r2)     sa[nt][2] = -1e30f;
                if (c + 1 > r2) sa[nt][3] = -1e30f;
            }
        }

        // Row max over this warp's 32 cols
        float mx1 = -1e30f, mx2 = -1e30f;
#pragma unroll
        for (int nt = 0; nt < 4; nt++) {
            mx1 = fmaxf(mx1, fmaxf(sa[nt][0], sa[nt][1]));
            mx2 = fmaxf(mx2, fmaxf(sa[nt][2], sa[nt][3]));
        }
        mx1 = fmaxf(mx1, __shfl_xor_sync(0xffffffffu, mx1, 1));
        mx1 = fmaxf(mx1, __shfl_xor_sync(0xffffffffu, mx1, 2));
        mx2 = fmaxf(mx2, __shfl_xor_sync(0xffffffffu, mx2, 1));
        mx2 = fmaxf(mx2, __shfl_xor_sync(0xffffffffu, mx2, 2));
        if (q4 == 0) {
            mx_s[r1 * 2 + wk] = mx1;
            mx_s[r2 * 2 + wk] = mx2;
        }
        __syncthreads();

        if (tid < 64) {
            float mo = m_s[tid];
            float mn = fmaxf(mo, fmaxf(mx_s[tid * 2], mx_s[tid * 2 + 1]));
            m_s[tid]  = mn;
            al_s[tid] = __expf(mo - mn);
        }
        __syncthreads();

        // p = exp(s - m); write P fp16; partial sums; rescale O
        const float m1 = m_s[r1], m2 = m_s[r2];
        float s1 = 0.f, s2 = 0.f;
#pragma unroll
        for (int nt = 0; nt < 4; nt++) {
            int c = wk * 32 + nt * 8 + q4 * 2;
            float p0 = __expf(sa[nt][0] - m1);
            float p1 = __expf(sa[nt][1] - m1);
            float p2 = __expf(sa[nt][2] - m2);
            float p3 = __expf(sa[nt][3] - m2);
            s1 += p0 + p1;
            s2 += p2 + p3;
            __half2 h1 = __floats2half2_rn(p0, p1);
            __half2 h2 = __floats2half2_rn(p2, p3);
            *(uint32_t*)(sm + OFF_P + r1 * (ASTR * 2) + c * 2) = *(uint32_t*)&h1;
            *(uint32_t*)(sm + OFF_P + r2 * (ASTR * 2) + c * 2) = *(uint32_t*)&h2;
        }
        s1 += __shfl_xor_sync(0xffffffffu, s1, 1);
        s1 += __shfl_xor_sync(0xffffffffu, s1, 2);
        s2 += __shfl_xor_sync(0xffffffffu, s2, 1);
        s2 += __shfl_xor_sync(0xffffffffu, s2, 2);
        if (q4 == 0) {
            su_s[r1 * 2 + wk] = s1;
            su_s[r2 * 2 + wk] = s2;
        }
        {
            const float a1 = al_s[r1], a2 = al_s[r2];
#pragma unroll
            for (int nt = 0; nt < 4; nt++) {
                O[nt][0] *= a1; O[nt][1] *= a1;
                O[nt][2] *= a2; O[nt][3] *= a2;
            }
        }
        __syncthreads();

        if (tid < 64)
            l_s[tid] = l_s[tid] * al_s[tid] + su_s[tid * 2] + su_s[tid * 2 + 1];

        // ---- O += P @ V ----
#pragma unroll
        for (int s = 0; s < 4; s++) {
            uint32_t af[4];
            ldsm4(af, sb + OFF_P + (wq * 16 + a_r16) * (ASTR * 2) + s * 32 + a_hi);
            uint32_t bf[4][2];
#pragma unroll
            for (int g = 0; g < 2; g++) {
                uint32_t r[4];
                ldsm4t(r, sb + OFF_V + (s * 16 + v_r) * (ASTR * 2) +
                          (wk * 32 + g * 16 + v_c) * 2);
                bf[2 * g][0] = r[0]; bf[2 * g][1] = r[1];
                bf[2 * g + 1][0] = r[2]; bf[2 * g + 1][1] = r[3];
            }
#pragma unroll
            for (int nt = 0; nt < 4; nt++)
                mma16816h(O[nt], af, bf[nt]);
        }
        __syncthreads();
    }

    // Finalize -> fp16 out
    const float li1 = 1.f / l_s[r1];
    const float li2 = 1.f / l_s[r2];
    __half* op = out + ((size_t)b * SEQ + q0) * DMODEL + h * HDIM;
#pragma unroll
    for (int nt = 0; nt < 4; nt++) {
        int c = wk * 32 + nt * 8 + q4 * 2;
        __half2 o1 = __floats2half2_rn(O[nt][0] * li1, O[nt][1] * li1);
        __half2 o2 = __floats2half2_rn(O[nt][2] * li2, O[nt][3] * li2);
        *(uint32_t*)(op + (size_t)r1 * DMODEL + c) = *(uint32_t*)&o1;
        *(uint32_t*)(op + (size_t)r2 * DMODEL + c) = *(uint32_t*)&o2;
    }
}

// ===========================================================================
// Launch
// ===========================================================================
extern "C" void kernel_launch(void* const* d_in, const int* in_sizes, int n_in,
                              void* d_out, int out_size) {
    const float* x    = (const float*)d_in[0];
    // d_in[1] = mask (tril) — causality applied analytically
    const float* Wqkv = (const float*)d_in[2];
    const float* Wout = (const float*)d_in[3];
    float* out = (float*)d_out;

    __half *xh, *qkv, *attnh, *wqkvT, *woutT;
    cudaGetSymbolAddress((void**)&xh, g_xh);
    cudaGetSymbolAddress((void**)&qkv, g_qkv);
    cudaGetSymbolAddress((void**)&attnh, g_attnh);
    cudaGetSymbolAddress((void**)&wqkvT, g_wqkvT);
    cudaGetSymbolAddress((void**)&woutT, g_woutT);

    cudaFuncSetAttribute(gemm_mma<true>, cudaFuncAttributeMaxDynamicSharedMemorySize,
                         GEMM_SMEM);
    cudaFuncSetAttribute(gemm_mma<false>, cudaFuncAttributeMaxDynamicSharedMemorySize,
                         GEMM_SMEM);
    cudaFuncSetAttribute(attn_mma, cudaFuncAttributeMaxDynamicSharedMemorySize,
                         ATT_SMEM);

    // 1. Convert inputs to fp16
    conv_h<<<(ROWS * DMODEL / 4) / 256, 256>>>(x, xh);
    transp_h<<<dim3(N3 / 32, DMODEL / 32), dim3(32, 8)>>>(Wqkv, wqkvT, DMODEL, N3);
    transp_h<<<dim3(DMODEL / 32, DMODEL / 32), dim3(32, 8)>>>(Wout, woutT, DMODEL, DMODEL);

    // 2. QKV projection (fp16 HMMA, K=1024), fp16 out
    gemm_mma<true><<<dim3(N3 / 128, ROWS / 128), 256, GEMM_SMEM>>>(xh, wqkvT, qkv,
                                                                   N3, DMODEL);

    // 3. Causal flash attention (fp16 tensor cores), fp16 out
    attn_mma<<<dim3(SEQ / 64, NHEADS, BATCH), 256, ATT_SMEM>>>(qkv, attnh);

    // 4. Output projection (fp16 HMMA, K=1024), fp32 out
    gemm_mma<false><<<dim3(DMODEL / 128, ROWS / 128), 256, GEMM_SMEM>>>(attnh, woutT, out,
                                                                        DMODEL, DMODEL);
}

// round 14
// speedup vs baseline: 5.2017x; 1.2271x over previous
#include <cuda_runtime.h>
#include <cuda_bf16.h>
#include <cuda_fp16.h>
#include <cstdint>
#include <math.h>

// Problem constants
#define BATCH 2
#define SEQ 2048
#define DMODEL 1024
#define NHEADS 16
#define HDIM 64
#define N3 (3 * DMODEL)
#define ROWS (BATCH * SEQ)   // 4096

// Scratch (fp16 pipeline)
__device__ __half g_xh[(size_t)ROWS * DMODEL];        // x in fp16
__device__ __half g_qkv[(size_t)ROWS * N3];           // QKV proj out, fp16
__device__ __half g_attnh[(size_t)ROWS * DMODEL];     // attention out, fp16
__device__ __half g_wqkvT[(size_t)N3 * DMODEL];       // Wqkv^T fp16 [3072,1024]
__device__ __half g_woutT[(size_t)DMODEL * DMODEL];   // Wout^T fp16 [1024,1024]

// ===========================================================================
// Helpers (sm_80-level PTX only — target is plain compute_103)
// ===========================================================================
__device__ __forceinline__ uint32_t smem_u32(const void* p) {
    uint32_t a;
    asm("{ .reg .u64 t; cvta.to.shared.u64 t, %1; cvt.u32.u64 %0, t; }"
        : "=r"(a) : "l"(p));
    return a;
}
__device__ __forceinline__ void cpasync16(uint32_t saddr, const void* gaddr) {
    asm volatile("cp.async.cg.shared.global [%0], [%1], 16;"
                 :: "r"(saddr), "l"(gaddr));
}
#define CP_COMMIT() asm volatile("cp.async.commit_group;" ::: "memory")
#define CP_WAIT2()  asm volatile("cp.async.wait_group 2;" ::: "memory")

__device__ __forceinline__ void ldsm4(uint32_t* r, uint32_t addr) {
    asm volatile("ldmatrix.sync.aligned.m8n8.x4.shared.b16 {%0,%1,%2,%3}, [%4];"
                 : "=r"(r[0]), "=r"(r[1]), "=r"(r[2]), "=r"(r[3]) : "r"(addr));
}
__device__ __forceinline__ void ldsm4t(uint32_t* r, uint32_t addr) {
    asm volatile("ldmatrix.sync.aligned.m8n8.x4.trans.shared.b16 {%0,%1,%2,%3}, [%4];"
                 : "=r"(r[0]), "=r"(r[1]), "=r"(r[2]), "=r"(r[3]) : "r"(addr));
}
// fp16 MMA, fp32 accum
__device__ __forceinline__ void mma16816h(float* c, const uint32_t* a, const uint32_t* b) {
    asm volatile(
        "mma.sync.aligned.m16n8k16.row.col.f32.f16.f16.f32 "
        "{%0,%1,%2,%3}, {%4,%5,%6,%7}, {%8,%9}, {%0,%1,%2,%3};"
        : "+f"(c[0]), "+f"(c[1]), "+f"(c[2]), "+f"(c[3])
        : "r"(a[0]), "r"(a[1]), "r"(a[2]), "r"(a[3]), "r"(b[0]), "r"(b[1]));
}

// ===========================================================================
// Convert kernels
// ===========================================================================
__global__ void conv_h(const float* __restrict__ in, __half* __restrict__ out) {
    int vi = blockIdx.x * blockDim.x + threadIdx.x;
    float4 v = *(const float4*)(in + (size_t)vi * 4);
    __half2 h0 = __floats2half2_rn(v.x, v.y);
    __half2 h1 = __floats2half2_rn(v.z, v.w);
    uint2 u = make_uint2(*(uint32_t*)&h0, *(uint32_t*)&h1);
    *(uint2*)(out + (size_t)vi * 4) = u;
}

__global__ void transp_h(const float* __restrict__ W, __half* __restrict__ Bt,
                         int K, int N) {
    __shared__ float t[32][33];
    int n0 = blockIdx.x * 32, k0 = blockIdx.y * 32;
    int tx = threadIdx.x, ty = threadIdx.y;   // block (32, 8)
#pragma unroll
    for (int i = 0; i < 4; i++)
        t[ty + 8 * i][tx] = W[(size_t)(k0 + ty + 8 * i) * N + n0 + tx];
    __syncthreads();
#pragma unroll
    for (int i = 0; i < 4; i++) {
        int n = n0 + ty + 8 * i;
        int k = k0 + tx;
        Bt[(size_t)n * K + k] = __float2half(t[tx][ty + 8 * i]);
    }
}

// ===========================================================================
// Warp-MMA GEMM: C[m][n] = sum_k A[m][k] * Bt[n][k]  (fp16 in, fp32/fp16 out)
// CTA tile 128x128, K-stage 32, 256 threads, 4-stage cp.async pipeline,
// 2 CTAs/SM (regs capped at 128), ONE barrier per K-iteration.
// ===========================================================================
#define GK 32
#define AROW 40
#define ATILE_B (128 * AROW * 2)
#define STAGE_B (2 * ATILE_B)
#define NSTAGE 4
#define GEMM_SMEM (NSTAGE * STAGE_B)

template <bool HALFOUT>
__global__ __launch_bounds__(256, 2)
void gemm_mma(const __half* __restrict__ A, const __half* __restrict__ Bt,
              void* __restrict__ Cv, int Nc, int KK) {
    extern __shared__ __align__(128) char smbuf[];
    const uint32_t sbase = smem_u32(smbuf);

    const int tid  = threadIdx.x;
    const int wid  = tid >> 5;
    const int lane = tid & 31;
    const int m0 = blockIdx.y * 128;
    const int n0 = blockIdx.x * 128;
    const int wm = wid & 3;
    const int wn = wid >> 2;

    float acc[2][8][4];
#pragma unroll
    for (int i = 0; i < 2; i++)
#pragma unroll
        for (int j = 0; j < 8; j++)
#pragma unroll
            for (int l = 0; l < 4; l++) acc[i][j][l] = 0.f;

    const int lrow = tid >> 1;
    const int lc   = (tid & 1) * 2;
    const int niter = KK / GK;

#define SM_A(st) (sbase + (st) * STAGE_B)
#define SM_B(st) (sbase + (st) * STAGE_B + ATILE_B)
#define LOAD_STAGE(st, it) do {                                               \
    const __half* ga = A + (size_t)(m0 + lrow) * KK + (size_t)(it) * GK + lc * 8; \
    const __half* gb = Bt + (size_t)(n0 + lrow) * KK + (size_t)(it) * GK + lc * 8; \
    uint32_t sa = SM_A(st) + lrow * (AROW * 2) + lc * 16;                     \
    uint32_t sb = SM_B(st) + lrow * (AROW * 2) + lc * 16;                     \
    cpasync16(sa, ga); cpasync16(sa + 16, ga + 8);                            \
    cpasync16(sb, gb); cpasync16(sb + 16, gb + 8);                            \
    CP_COMMIT();                                                              \
} while (0)

    LOAD_STAGE(0, 0);
    LOAD_STAGE(1, 1);
    LOAD_STAGE(2, 2);

    const int a_r16 = lane & 15;
    const int a_hi  = (lane & 16) ? 16 : 0;
    const int b_r   = (lane & 7) + ((lane & 16) ? 8 : 0);
    const int b_hi  = (lane & 8) ? 16 : 0;

    for (int it = 0; it < niter; it++) {
        const int st = it & (NSTAGE - 1);
        CP_WAIT2();
        // Single barrier: makes stage `st` (copied by all threads) visible, AND
        // guarantees every warp finished computing stage (it-1)%4 — which is the
        // buffer the loads below will overwrite ((it+3)%4 == (it-1)%4).
        __syncthreads();

        const uint32_t ab = SM_A(st);
        const uint32_t bb = SM_B(st);
#pragma unroll
        for (int s = 0; s < 2; s++) {
            uint32_t a0[4], a1[4];
            ldsm4(a0, ab + (wm * 32 + a_r16) * (AROW * 2) + s * 32 + a_hi);
            ldsm4(a1, ab + (wm * 32 + 16 + a_r16) * (AROW * 2) + s * 32 + a_hi);
            uint32_t bf[8][2];
#pragma unroll
            for (int g = 0; g < 4; g++) {
                uint32_t r[4];
                ldsm4(r, bb + (wn * 64 + g * 16 + b_r) * (AROW * 2) + s * 32 + b_hi);
                bf[2 * g][0] = r[0]; bf[2 * g][1] = r[1];
                bf[2 * g + 1][0] = r[2]; bf[2 * g + 1][1] = r[3];
            }
#pragma unroll
            for (int nt = 0; nt < 8; nt++) {
                mma16816h(acc[0][nt], a0, bf[nt]);
                mma16816h(acc[1][nt], a1, bf[nt]);
            }
        }

        if (it + 3 < niter) LOAD_STAGE((it + 3) & (NSTAGE - 1), it + 3);
        else CP_COMMIT();   // keep group count uniform for CP_WAIT2
    }

    const int g4 = lane >> 2;
    const int q4 = lane & 3;
#pragma unroll
    for (int mt = 0; mt < 2; mt++) {
        int r0 = m0 + wm * 32 + mt * 16 + g4;
#pragma unroll
        for (int nt = 0; nt < 8; nt++) {
            int cc = n0 + wn * 64 + nt * 8 + q4 * 2;
            if (HALFOUT) {
                __half* Cb = (__half*)Cv;
                __half2 p0 = __floats2half2_rn(acc[mt][nt][0], acc[mt][nt][1]);
                __half2 p1 = __floats2half2_rn(acc[mt][nt][2], acc[mt][nt][3]);
                *(uint32_t*)(Cb + (size_t)r0 * Nc + cc) = *(uint32_t*)&p0;
                *(uint32_t*)(Cb + (size_t)(r0 + 8) * Nc + cc) = *(uint32_t*)&p1;
            } else {
                float* Cf = (float*)Cv;
                *(float2*)(Cf + (size_t)r0 * Nc + cc) =
                    make_float2(acc[mt][nt][0], acc[mt][nt][1]);
                *(float2*)(Cf + (size_t)(r0 + 8) * Nc + cc) =
                    make_float2(acc[mt][nt][2], acc[mt][nt][3]);
            }
        }
    }
#undef LOAD_STAGE
#undef SM_A
#undef SM_B
}

// ===========================================================================
// Tensor-core flash attention (causal), fp16 MMA + fp32 softmax, fp16 out.
// Grid (SEQ/64, NHEADS, BATCH), 256 threads (8 warps: 4 over q x 2 over k/d).
// ===========================================================================
#define ASTR 72                         // smem row stride in halves (144 B)
#define ATILE_BYTES (64 * ASTR * 2)     // 9216
#define OFF_Q  0
#define OFF_K  ATILE_BYTES
#define OFF_V  (2 * ATILE_BYTES)
#define OFF_P  (3 * ATILE_BYTES)
#define OFF_MX (4 * ATILE_BYTES)             // float[64][2]
#define OFF_SU (OFF_MX + 512)                // float[64][2]
#define OFF_M  (OFF_SU + 512)                // float[64]
#define OFF_L  (OFF_M + 256)                 // float[64]
#define OFF_AL (OFF_L + 256)                 // float[64]
#define ATT_SMEM (OFF_AL + 256)

__global__ __launch_bounds__(256)
void attn_mma(const __half* __restrict__ qkv, __half* __restrict__ out) {
    extern __shared__ __align__(128) char sm[];
    const uint32_t sb = smem_u32(sm);
    float* mx_s = (float*)(sm + OFF_MX);
    float* su_s = (float*)(sm + OFF_SU);
    float* m_s  = (float*)(sm + OFF_M);
    float* l_s  = (float*)(sm + OFF_L);
    float* al_s = (float*)(sm + OFF_AL);

    const int tid  = threadIdx.x;
    const int wid  = tid >> 5;
    const int lane = tid & 31;
    const int wq = wid & 3;        // q-slice (16 rows)
    const int wk = wid >> 2;       // k/d-slice (32 cols)
    const int g4 = lane >> 2;
    const int q4 = lane & 3;
    // Longest blocks (largest qb) first — better wave packing for causal skew
    const int qb = gridDim.x - 1 - blockIdx.x;
    const int h  = blockIdx.y;
    const int b  = blockIdx.z;
    const int q0 = qb * 64;

    const __half* base = qkv + (size_t)b * SEQ * N3;
    const __half* qp = base + (size_t)q0 * N3 + h * HDIM;

    const int a_r16 = lane & 15;
    const int a_hi  = (lane & 16) ? 16 : 0;
    const int b_r   = (lane & 7) + ((lane & 16) ? 8 : 0);
    const int b_hi  = (lane & 8) ? 16 : 0;
    const int v_r   = (lane & 7) + ((lane & 8) ? 8 : 0);
    const int v_c   = (lane & 16) ? 8 : 0;

    // Load Q tile (64 rows x 64 fp16)
#pragma unroll
    for (int l = 0; l < 2; l++) {
        int idx = tid + l * 256;
        int row = idx >> 3;
        int dc  = (idx & 7) * 8;
        uint4 v = *(const uint4*)(qp + (size_t)row * N3 + dc);
        *(uint4*)(sm + OFF_Q + row * (ASTR * 2) + dc * 2) = v;
    }
    if (tid < 64) { m_s[tid] = -1e30f; l_s[tid] = 0.f; }

    float O[4][4];
#pragma unroll
    for (int i = 0; i < 4; i++)
#pragma unroll
        for (int j = 0; j < 4; j++) O[i][j] = 0.f;

    const int r1 = wq * 16 + g4;
    const int r2 = r1 + 8;

    __syncthreads();

    for (int jt = 0; jt <= qb; jt++) {
        const int k0 = jt * 64;
        const __half* kp = base + (size_t)k0 * N3 + DMODEL + h * HDIM;
        const __half* vp = base + (size_t)k0 * N3 + 2 * DMODEL + h * HDIM;

#pragma unroll
        for (int l = 0; l < 2; l++) {
            int idx = tid + l * 256;
            int row = idx >> 3;
            int dc  = (idx & 7) * 8;
            uint4 kv = *(const uint4*)(kp + (size_t)row * N3 + dc);
            uint4 vv = *(const uint4*)(vp + (size_t)row * N3 + dc);
            *(uint4*)(sm + OFF_K + row * (ASTR * 2) + dc * 2) = kv;
            *(uint4*)(sm + OFF_V + row * (ASTR * 2) + dc * 2) = vv;
        }
        __syncthreads();

        // ---- S = Q @ K^T ----
        float sa[4][4];
#pragma unroll
        for (int nt = 0; nt < 4; nt++)
#pragma unroll
            for (int j = 0; j < 4; j++) sa[nt][j] = 0.f;

#pragma unroll
        for (int s = 0; s < 4; s++) {
            uint32_t af[4];
            ldsm4(af, sb + OFF_Q + (wq * 16 + a_r16) * (ASTR * 2) + s * 32 + a_hi);
            uint32_t bf[4][2];
#pragma unroll
            for (int g = 0; g < 2; g++) {
                uint32_t r[4];
                ldsm4(r, sb + OFF_K + (wk * 32 + g * 16 + b_r) * (ASTR * 2) + s * 32 + b_hi);
                bf[2 * g][0] = r[0]; bf[2 * g][1] = r[1];
                bf[2 * g + 1][0] = r[2]; bf[2 * g + 1][1] = r[3];
            }
#pragma unroll
            for (int nt = 0; nt < 4; nt++)
                mma16816h(sa[nt], af, bf[nt]);
        }

        // Scale + causal mask
        const bool diag = (jt == qb);
#pragma unroll
        for (int nt = 0; nt < 4; nt++) {
            int c = wk * 32 + nt * 8 + q4 * 2;
            sa[nt][0] *= 0.125f; sa[nt][1] *= 0.125f;
            sa[nt][2] *= 0.125f; sa[nt][3] *= 0.125f;
            if (diag) {
                if (c > r1)     sa[nt][0] = -1e30f;
                if (c + 1 > r1) sa[nt][1] = -1e30f;
                if (c > r2)     sa[nt][2] = -1e30f;
                if (c + 1 > r2) sa[nt][3] = -1e30f;
            }
        }

        // Row max over this warp's 32 cols
        float mx1 = -1e30f, mx2 = -1e30f;
#pragma unroll
        for (int nt = 0; nt < 4; nt++) {
            mx1 = fmaxf(mx1, fmaxf(sa[nt][0], sa[nt][1]));
            mx2 = fmaxf(mx2, fmaxf(sa[nt][2], sa[nt][3]));
        }
        mx1 = fmaxf(mx1, __shfl_xor_sync(0xffffffffu, mx1, 1));
        mx1 = fmaxf(mx1, __shfl_xor_sync(0xffffffffu, mx1, 2));
        mx2 = fmaxf(mx2, __shfl_xor_sync(0xffffffffu, mx2, 1));
        mx2 = fmaxf(mx2, __shfl_xor_sync(0xffffffffu, mx2, 2));
        if (q4 == 0) {
            mx_s[r1 * 2 + wk] = mx1;
            mx_s[r2 * 2 + wk] = mx2;
        }
        __syncthreads();

        if (tid < 64) {
            float mo = m_s[tid];
            float mn = fmaxf(mo, fmaxf(mx_s[tid * 2], mx_s[tid * 2 + 1]));
            m_s[tid]  = mn;
            al_s[tid] = __expf(mo - mn);
        }
        __syncthreads();

        // p = exp(s - m); write P fp16; partial sums; rescale O
        const float m1 = m_s[r1], m2 = m_s[r2];
        float s1 = 0.f, s2 = 0.f;
#pragma unroll
        for (int nt = 0; nt < 4; nt++) {
            int c = wk * 32 + nt * 8 + q4 * 2;
            float p0 = __expf(sa[nt][0] - m1);
            float p1 = __expf(sa[nt][1] - m1);
            float p2 = __expf(sa[nt][2] - m2);
            float p3 = __expf(sa[nt][3] - m2);
            s1 += p0 + p1;
            s2 += p2 + p3;
            __half2 h1 = __floats2half2_rn(p0, p1);
            __half2 h2 = __floats2half2_rn(p2, p3);
            *(uint32_t*)(sm + OFF_P + r1 * (ASTR * 2) + c * 2) = *(uint32_t*)&h1;
            *(uint32_t*)(sm + OFF_P + r2 * (ASTR * 2) + c * 2) = *(uint32_t*)&h2;
        }
        s1 += __shfl_xor_sync(0xffffffffu, s1, 1);
        s1 += __shfl_xor_sync(0xffffffffu, s1, 2);
        s2 += __shfl_xor_sync(0xffffffffu, s2, 1);
        s2 += __shfl_xor_sync(0xffffffffu, s2, 2);
        if (q4 == 0) {
            su_s[r1 * 2 + wk] = s1;
            su_s[r2 * 2 + wk] = s2;
        }
        {
            const float a1 = al_s[r1], a2 = al_s[r2];
#pragma unroll
            for (int nt = 0; nt < 4; nt++) {
                O[nt][0] *= a1; O[nt][1] *= a1;
                O[nt][2] *= a2; O[nt][3] *= a2;
            }
        }
        __syncthreads();

        if (tid < 64)
            l_s[tid] = l_s[tid] * al_s[tid] + su_s[tid * 2] + su_s[tid * 2 + 1];

        // ---- O += P @ V ----
#pragma unroll
        for (int s = 0; s < 4; s++) {
            uint32_t af[4];
            ldsm4(af, sb + OFF_P + (wq * 16 + a_r16) * (ASTR * 2) + s * 32 + a_hi);
            uint32_t bf[4][2];
#pragma unroll
            for (int g = 0; g < 2; g++) {
                uint32_t r[4];
                ldsm4t(r, sb + OFF_V + (s * 16 + v_r) * (ASTR * 2) +
                          (wk * 32 + g * 16 + v_c) * 2);
                bf[2 * g][0] = r[0]; bf[2 * g][1] = r[1];
                bf[2 * g + 1][0] = r[2]; bf[2 * g + 1][1] = r[3];
            }
#pragma unroll
            for (int nt = 0; nt < 4; nt++)
                mma16816h(O[nt], af, bf[nt]);
        }
        __syncthreads();
    }

    // Finalize -> fp16 out
    const float li1 = 1.f / l_s[r1];
    const float li2 = 1.f / l_s[r2];
    __half* op = out + ((size_t)b * SEQ + q0) * DMODEL + h * HDIM;
#pragma unroll
    for (int nt = 0; nt < 4; nt++) {
        int c = wk * 32 + nt * 8 + q4 * 2;
        __half2 o1 = __floats2half2_rn(O[nt][0] * li1, O[nt][1] * li1);
        __half2 o2 = __floats2half2_rn(O[nt][2] * li2, O[nt][3] * li2);
        *(uint32_t*)(op + (size_t)r1 * DMODEL + c) = *(uint32_t*)&o1;
        *(uint32_t*)(op + (size_t)r2 * DMODEL + c) = *(uint32_t*)&o2;
    }
}

// ===========================================================================
// Launch
// ===========================================================================
extern "C" void kernel_launch(void* const* d_in, const int* in_sizes, int n_in,
                              void* d_out, int out_size) {
    const float* x    = (const float*)d_in[0];
    // d_in[1] = mask (tril) — causality applied analytically
    const float* Wqkv = (const float*)d_in[2];
    const float* Wout = (const float*)d_in[3];
    float* out = (float*)d_out;

    __half *xh, *qkv, *attnh, *wqkvT, *woutT;
    cudaGetSymbolAddress((void**)&xh, g_xh);
    cudaGetSymbolAddress((void**)&qkv, g_qkv);
    cudaGetSymbolAddress((void**)&attnh, g_attnh);
    cudaGetSymbolAddress((void**)&wqkvT, g_wqkvT);
    cudaGetSymbolAddress((void**)&woutT, g_woutT);

    cudaFuncSetAttribute(gemm_mma<true>, cudaFuncAttributeMaxDynamicSharedMemorySize,
                         GEMM_SMEM);
    cudaFuncSetAttribute(gemm_mma<false>, cudaFuncAttributeMaxDynamicSharedMemorySize,
                         GEMM_SMEM);
    cudaFuncSetAttribute(attn_mma, cudaFuncAttributeMaxDynamicSharedMemorySize,
                         ATT_SMEM);

    // 1. Convert inputs to fp16
    conv_h<<<(ROWS * DMODEL / 4) / 256, 256>>>(x, xh);
    transp_h<<<dim3(N3 / 32, DMODEL / 32), dim3(32, 8)>>>(Wqkv, wqkvT, DMODEL, N3);
    transp_h<<<dim3(DMODEL / 32, DMODEL / 32), dim3(32, 8)>>>(Wout, woutT, DMODEL, DMODEL);

    // 2. QKV projection (fp16 HMMA, K=1024), fp16 out
    gemm_mma<true><<<dim3(N3 / 128, ROWS / 128), 256, GEMM_SMEM>>>(xh, wqkvT, qkv,
                                                                   N3, DMODEL);

    // 3. Causal flash attention (fp16 tensor cores), fp16 out
    attn_mma<<<dim3(SEQ / 64, NHEADS, BATCH), 256, ATT_SMEM>>>(qkv, attnh);

    // 4. Output projection (fp16 HMMA, K=1024), fp32 out
    gemm_mma<false><<<dim3(DMODEL / 128, ROWS / 128), 256, GEMM_SMEM>>>(attnh, woutT, out,
                                                                        DMODEL, DMODEL);
}

// round 15
// speedup vs baseline: 5.8063x; 1.1162x over previous
#include <cuda_runtime.h>
#include <cuda_bf16.h>
#include <cuda_fp16.h>
#include <cstdint>
#include <math.h>

// Problem constants
#define BATCH 2
#define SEQ 2048
#define DMODEL 1024
#define NHEADS 16
#define HDIM 64
#define N3 (3 * DMODEL)
#define ROWS (BATCH * SEQ)   // 4096

// Scratch (fp16 pipeline)
__device__ __half g_xh[(size_t)ROWS * DMODEL];        // x in fp16
__device__ __half g_qkv[(size_t)ROWS * N3];           // QKV proj out, fp16
__device__ __half g_attnh[(size_t)ROWS * DMODEL];     // attention out, fp16
__device__ __half g_wqkvT[(size_t)N3 * DMODEL];       // Wqkv^T fp16 [3072,1024]
__device__ __half g_woutT[(size_t)DMODEL * DMODEL];   // Wout^T fp16 [1024,1024]

// ===========================================================================
// Helpers (sm_80-level PTX only — target is plain compute_103)
// ===========================================================================
__device__ __forceinline__ uint32_t smem_u32(const void* p) {
    uint32_t a;
    asm("{ .reg .u64 t; cvta.to.shared.u64 t, %1; cvt.u32.u64 %0, t; }"
        : "=r"(a) : "l"(p));
    return a;
}
__device__ __forceinline__ void cpasync16(uint32_t saddr, const void* gaddr) {
    asm volatile("cp.async.cg.shared.global [%0], [%1], 16;"
                 :: "r"(saddr), "l"(gaddr));
}
#define CP_COMMIT() asm volatile("cp.async.commit_group;" ::: "memory")
#define CP_WAIT1()  asm volatile("cp.async.wait_group 1;" ::: "memory")
#define CP_WAIT0()  asm volatile("cp.async.wait_group 0;" ::: "memory")

__device__ __forceinline__ void ldsm4(uint32_t* r, uint32_t addr) {
    asm volatile("ldmatrix.sync.aligned.m8n8.x4.shared.b16 {%0,%1,%2,%3}, [%4];"
                 : "=r"(r[0]), "=r"(r[1]), "=r"(r[2]), "=r"(r[3]) : "r"(addr));
}
__device__ __forceinline__ void ldsm4t(uint32_t* r, uint32_t addr) {
    asm volatile("ldmatrix.sync.aligned.m8n8.x4.trans.shared.b16 {%0,%1,%2,%3}, [%4];"
                 : "=r"(r[0]), "=r"(r[1]), "=r"(r[2]), "=r"(r[3]) : "r"(addr));
}
// fp16 MMA, fp32 accum
__device__ __forceinline__ void mma16816h(float* c, const uint32_t* a, const uint32_t* b) {
    asm volatile(
        "mma.sync.aligned.m16n8k16.row.col.f32.f16.f16.f32 "
        "{%0,%1,%2,%3}, {%4,%5,%6,%7}, {%8,%9}, {%0,%1,%2,%3};"
        : "+f"(c[0]), "+f"(c[1]), "+f"(c[2]), "+f"(c[3])
        : "r"(a[0]), "r"(a[1]), "r"(a[2]), "r"(a[3]), "r"(b[0]), "r"(b[1]));
}
__device__ __forceinline__ uint32_t pack_h2(float a, float b) {
    __half2 h = __floats2half2_rn(a, b);
    return *(uint32_t*)&h;
}

// ===========================================================================
// Convert kernels
// ===========================================================================
__global__ void conv_h(const float* __restrict__ in, __half* __restrict__ out) {
    int vi = blockIdx.x * blockDim.x + threadIdx.x;
    float4 v = *(const float4*)(in + (size_t)vi * 4);
    __half2 h0 = __floats2half2_rn(v.x, v.y);
    __half2 h1 = __floats2half2_rn(v.z, v.w);
    uint2 u = make_uint2(*(uint32_t*)&h0, *(uint32_t*)&h1);
    *(uint2*)(out + (size_t)vi * 4) = u;
}

__global__ void transp_h(const float* __restrict__ W, __half* __restrict__ Bt,
                         int K, int N) {
    __shared__ float t[32][33];
    int n0 = blockIdx.x * 32, k0 = blockIdx.y * 32;
    int tx = threadIdx.x, ty = threadIdx.y;   // block (32, 8)
#pragma unroll
    for (int i = 0; i < 4; i++)
        t[ty + 8 * i][tx] = W[(size_t)(k0 + ty + 8 * i) * N + n0 + tx];
    __syncthreads();
#pragma unroll
    for (int i = 0; i < 4; i++) {
        int n = n0 + ty + 8 * i;
        int k = k0 + tx;
        Bt[(size_t)n * K + k] = __float2half(t[tx][ty + 8 * i]);
    }
}

// ===========================================================================
// Warp-MMA GEMM: C[m][n] = sum_k A[m][k] * Bt[n][k]  (fp16 in, fp32/fp16 out)
// CTA tile 128x128, K-stage 64, 256 threads, 3-stage cp.async pipeline,
// 2 CTAs/SM, ONE barrier per K-iteration (16 iterations at K=1024).
// ===========================================================================
#define GK 64
#define GROW 72                      // halves per smem row (144 B)
#define GTILE (128 * GROW * 2)       // 18432 B
#define GSTAGE (2 * GTILE)           // 36864 B (A + B)
#define GNST 3
#define GEMM_SMEM (GNST * GSTAGE)    // 110592 B

template <bool HALFOUT>
__global__ __launch_bounds__(256, 2)
void gemm_mma(const __half* __restrict__ A, const __half* __restrict__ Bt,
              void* __restrict__ Cv, int Nc, int KK) {
    extern __shared__ __align__(128) char smbuf[];
    const uint32_t sbase = smem_u32(smbuf);

    const int tid  = threadIdx.x;
    const int wid  = tid >> 5;
    const int lane = tid & 31;
    const int m0 = blockIdx.y * 128;
    const int n0 = blockIdx.x * 128;
    const int wm = wid & 3;
    const int wn = wid >> 2;

    float acc[2][8][4];
#pragma unroll
    for (int i = 0; i < 2; i++)
#pragma unroll
        for (int j = 0; j < 8; j++)
#pragma unroll
            for (int l = 0; l < 4; l++) acc[i][j][l] = 0.f;

    const int lrow  = tid >> 1;          // 0..127
    const int lhalf = (tid & 1) * 32;    // half-offset within 64-half row
    const int niter = KK / GK;           // 16

#define SM_A(st) (sbase + (st) * GSTAGE)
#define SM_B(st) (sbase + (st) * GSTAGE + GTILE)
#define LOAD_STAGE(st, it) do {                                               \
    const __half* ga = A + (size_t)(m0 + lrow) * KK + (size_t)(it) * GK + lhalf; \
    const __half* gb = Bt + (size_t)(n0 + lrow) * KK + (size_t)(it) * GK + lhalf; \
    uint32_t sa_ = SM_A(st) + lrow * (GROW * 2) + lhalf * 2;                  \
    uint32_t sb_ = SM_B(st) + lrow * (GROW * 2) + lhalf * 2;                  \
    cpasync16(sa_,      ga);      cpasync16(sa_ + 16, ga + 8);                \
    cpasync16(sa_ + 32, ga + 16); cpasync16(sa_ + 48, ga + 24);               \
    cpasync16(sb_,      gb);      cpasync16(sb_ + 16, gb + 8);                \
    cpasync16(sb_ + 32, gb + 16); cpasync16(sb_ + 48, gb + 24);               \
    CP_COMMIT();                                                              \
} while (0)

    LOAD_STAGE(0, 0);
    LOAD_STAGE(1, 1);

    const int a_r16 = lane & 15;
    const int a_hi  = (lane & 16) ? 16 : 0;
    const int b_r   = (lane & 7) + ((lane & 16) ? 8 : 0);
    const int b_hi  = (lane & 8) ? 16 : 0;

    int st = 0, st_ld = 2;
    for (int it = 0; it < niter; it++) {
        CP_WAIT1();
        __syncthreads();   // stage `st` visible; all warps done with stage being reloaded

        const uint32_t ab = SM_A(st);
        const uint32_t bb = SM_B(st);
#pragma unroll
        for (int s = 0; s < 4; s++) {           // four k16 steps (GK=64)
            uint32_t a0[4], a1[4];
            ldsm4(a0, ab + (wm * 32 + a_r16) * (GROW * 2) + s * 32 + a_hi);
            ldsm4(a1, ab + (wm * 32 + 16 + a_r16) * (GROW * 2) + s * 32 + a_hi);
            uint32_t bf[8][2];
#pragma unroll
            for (int g = 0; g < 4; g++) {
                uint32_t r[4];
                ldsm4(r, bb + (wn * 64 + g * 16 + b_r) * (GROW * 2) + s * 32 + b_hi);
                bf[2 * g][0] = r[0]; bf[2 * g][1] = r[1];
                bf[2 * g + 1][0] = r[2]; bf[2 * g + 1][1] = r[3];
            }
#pragma unroll
            for (int nt = 0; nt < 8; nt++) {
                mma16816h(acc[0][nt], a0, bf[nt]);
                mma16816h(acc[1][nt], a1, bf[nt]);
            }
        }

        if (it + 2 < niter) {
            LOAD_STAGE(st_ld, it + 2);
            st_ld = (st_ld == 2) ? 0 : st_ld + 1;
        } else {
            CP_COMMIT();   // keep group count uniform for CP_WAIT1
        }
        st = (st == 2) ? 0 : st + 1;
    }

    const int g4 = lane >> 2;
    const int q4 = lane & 3;
#pragma unroll
    for (int mt = 0; mt < 2; mt++) {
        int r0 = m0 + wm * 32 + mt * 16 + g4;
#pragma unroll
        for (int nt = 0; nt < 8; nt++) {
            int cc = n0 + wn * 64 + nt * 8 + q4 * 2;
            if (HALFOUT) {
                __half* Cb = (__half*)Cv;
                *(uint32_t*)(Cb + (size_t)r0 * Nc + cc) =
                    pack_h2(acc[mt][nt][0], acc[mt][nt][1]);
                *(uint32_t*)(Cb + (size_t)(r0 + 8) * Nc + cc) =
                    pack_h2(acc[mt][nt][2], acc[mt][nt][3]);
            } else {
                float* Cf = (float*)Cv;
                *(float2*)(Cf + (size_t)r0 * Nc + cc) =
                    make_float2(acc[mt][nt][0], acc[mt][nt][1]);
                *(float2*)(Cf + (size_t)(r0 + 8) * Nc + cc) =
                    make_float2(acc[mt][nt][2], acc[mt][nt][3]);
            }
        }
    }
#undef LOAD_STAGE
#undef SM_A
#undef SM_B
}

// ===========================================================================
// FA2-style tensor-core flash attention (causal), fp16 MMA + fp32 softmax.
// Grid (SEQ/64, NHEADS, BATCH), 128 threads = 4 warps; each warp owns 16 q-rows
// across the full 64-key tile. Softmax stats in registers (quad shuffles only).
// P stays in registers: S C-frags reinterpret directly as P@V A-frags.
// K/V double-buffered with cp.async prefetch; ONE barrier per k-tile.
// ===========================================================================
#define FA_ASTR 72                       // halves per smem row (144 B)
#define FA_TILE (64 * FA_ASTR * 2)       // 9216 B
#define FA_Q   0
#define FA_KV  FA_TILE                   // 4 tiles: K0,V0,K1,V1
#define FA_SMEM (FA_KV + 4 * FA_TILE)    // 46080 B

__global__ __launch_bounds__(128)
void attn_mma(const __half* __restrict__ qkv, __half* __restrict__ out) {
    extern __shared__ __align__(128) char sm[];
    const uint32_t sb = smem_u32(sm);

    const int tid  = threadIdx.x;
    const int wid  = tid >> 5;          // 0..3: q-slice of 16 rows
    const int lane = tid & 31;
    const int g4 = lane >> 2;
    const int q4 = lane & 3;
    // Longest causal blocks first — better wave packing
    const int qb = gridDim.x - 1 - blockIdx.x;
    const int h  = blockIdx.y;
    const int b  = blockIdx.z;
    const int q0 = qb * 64;

    const __half* base = qkv + (size_t)b * SEQ * N3;
    const __half* qp = base + (size_t)q0 * N3 + h * HDIM;

    const int a_r16 = lane & 15;
    const int a_hi  = (lane & 16) ? 16 : 0;
    const int b_r   = (lane & 7) + ((lane & 16) ? 8 : 0);
    const int b_hi  = (lane & 8) ? 16 : 0;
    const int v_r   = (lane & 7) + ((lane & 8) ? 8 : 0);
    const int v_c   = (lane & 16) ? 8 : 0;

    // Prefetch K/V tile 0 (cp.async) and load Q tile (plain)
    {
        const __half* kp = base + (size_t)0 * N3 + DMODEL + h * HDIM;
        const __half* vp = base + (size_t)0 * N3 + 2 * DMODEL + h * HDIM;
#pragma unroll
        for (int l = 0; l < 4; l++) {
            int idx = tid + l * 128;
            int row = idx >> 3;
            int dc  = (idx & 7) * 8;
            cpasync16(sb + FA_KV + row * (FA_ASTR * 2) + dc * 2,
                      kp + (size_t)row * N3 + dc);
            cpasync16(sb + FA_KV + FA_TILE + row * (FA_ASTR * 2) + dc * 2,
                      vp + (size_t)row * N3 + dc);
        }
        CP_COMMIT();
#pragma unroll
        for (int l = 0; l < 4; l++) {
            int idx = tid + l * 128;
            int row = idx >> 3;
            int dc  = (idx & 7) * 8;
            uint4 v = *(const uint4*)(qp + (size_t)row * N3 + dc);
            *(uint4*)(sm + FA_Q + row * (FA_ASTR * 2) + dc * 2) = v;
        }
        CP_WAIT0();
    }
    __syncthreads();

    // Q A-frags: held in registers for the whole kernel
    uint32_t qf[4][4];
#pragma unroll
    for (int s = 0; s < 4; s++)
        ldsm4(qf[s], sb + FA_Q + (wid * 16 + a_r16) * (FA_ASTR * 2) + s * 32 + a_hi);

    float O[8][4];
#pragma unroll
    for (int nt = 0; nt < 8; nt++)
#pragma unroll
        for (int j = 0; j < 4; j++) O[nt][j] = 0.f;

    float m1 = -1e30f, m2 = -1e30f, l1 = 0.f, l2 = 0.f;
    const int row1 = wid * 16 + g4;      // local q rows owned by this thread
    const int row2 = row1 + 8;

    for (int jt = 0; jt <= qb; jt++) {
        const int buf = jt & 1;
        const uint32_t kb = sb + FA_KV + buf * 2 * FA_TILE;
        const uint32_t vb = kb + FA_TILE;

        // Prefetch next K/V tile while computing this one
        if (jt < qb) {
            const int nbuf = buf ^ 1;
            const __half* kp = base + (size_t)(jt + 1) * 64 * N3 + DMODEL + h * HDIM;
            const __half* vp = base + (size_t)(jt + 1) * 64 * N3 + 2 * DMODEL + h * HDIM;
#pragma unroll
            for (int l = 0; l < 4; l++) {
                int idx = tid + l * 128;
                int row = idx >> 3;
                int dc  = (idx & 7) * 8;
                cpasync16(sb + FA_KV + nbuf * 2 * FA_TILE + row * (FA_ASTR * 2) + dc * 2,
                          kp + (size_t)row * N3 + dc);
                cpasync16(sb + FA_KV + nbuf * 2 * FA_TILE + FA_TILE +
                              row * (FA_ASTR * 2) + dc * 2,
                          vp + (size_t)row * N3 + dc);
            }
            CP_COMMIT();
        }

        // ---- S = Q @ K^T : 16 q-rows x 64 keys ----
        float sa[8][4];
#pragma unroll
        for (int nt = 0; nt < 8; nt++)
#pragma unroll
            for (int j = 0; j < 4; j++) sa[nt][j] = 0.f;

#pragma unroll
        for (int s = 0; s < 4; s++) {
            uint32_t bf[8][2];
#pragma unroll
            for (int g = 0; g < 4; g++) {
                uint32_t r[4];
                ldsm4(r, kb + (g * 16 + b_r) * (FA_ASTR * 2) + s * 32 + b_hi);
                bf[2 * g][0] = r[0]; bf[2 * g][1] = r[1];
                bf[2 * g + 1][0] = r[2]; bf[2 * g + 1][1] = r[3];
            }
#pragma unroll
            for (int nt = 0; nt < 8; nt++)
                mma16816h(sa[nt], qf[s], bf[nt]);
        }

        // Scale + causal mask
        const bool diag = (jt == qb);
#pragma unroll
        for (int nt = 0; nt < 8; nt++) {
            sa[nt][0] *= 0.125f; sa[nt][1] *= 0.125f;
            sa[nt][2] *= 0.125f; sa[nt][3] *= 0.125f;
            if (diag) {
                int c = nt * 8 + q4 * 2;
                if (c > row1)     sa[nt][0] = -1e30f;
                if (c + 1 > row1) sa[nt][1] = -1e30f;
                if (c > row2)     sa[nt][2] = -1e30f;
                if (c + 1 > row2) sa[nt][3] = -1e30f;
            }
        }

        // Row max: in-thread over 8 groups, then quad shuffles (q4 bits)
        float mx1 = -1e30f, mx2 = -1e30f;
#pragma unroll
        for (int nt = 0; nt < 8; nt++) {
            mx1 = fmaxf(mx1, fmaxf(sa[nt][0], sa[nt][1]));
            mx2 = fmaxf(mx2, fmaxf(sa[nt][2], sa[nt][3]));
        }
        mx1 = fmaxf(mx1, __shfl_xor_sync(0xffffffffu, mx1, 1));
        mx1 = fmaxf(mx1, __shfl_xor_sync(0xffffffffu, mx1, 2));
        mx2 = fmaxf(mx2, __shfl_xor_sync(0xffffffffu, mx2, 1));
        mx2 = fmaxf(mx2, __shfl_xor_sync(0xffffffffu, mx2, 2));

        const float mn1 = fmaxf(m1, mx1);
        const float mn2 = fmaxf(m2, mx2);
        const float al1 = __expf(m1 - mn1);
        const float al2 = __expf(m2 - mn2);
        m1 = mn1; m2 = mn2;

        // exp; build P A-frags in registers (C-frag layout == A-frag layout);
        // accumulate row sums
        uint32_t ph[4][4];
        float s1 = 0.f, s2 = 0.f;
#pragma unroll
        for (int s = 0; s < 4; s++) {
            float p00 = __expf(sa[2 * s][0] - m1);
            float p01 = __expf(sa[2 * s][1] - m1);
            float p02 = __expf(sa[2 * s][2] - m2);
            float p03 = __expf(sa[2 * s][3] - m2);
            float p10 = __expf(sa[2 * s + 1][0] - m1);
            float p11 = __expf(sa[2 * s + 1][1] - m1);
            float p12 = __expf(sa[2 * s + 1][2] - m2);
            float p13 = __expf(sa[2 * s + 1][3] - m2);
            s1 += p00 + p01 + p10 + p11;
            s2 += p02 + p03 + p12 + p13;
            ph[s][0] = pack_h2(p00, p01);
            ph[s][1] = pack_h2(p02, p03);
            ph[s][2] = pack_h2(p10, p11);
            ph[s][3] = pack_h2(p12, p13);
        }
        s1 += __shfl_xor_sync(0xffffffffu, s1, 1);
        s1 += __shfl_xor_sync(0xffffffffu, s1, 2);
        s2 += __shfl_xor_sync(0xffffffffu, s2, 1);
        s2 += __shfl_xor_sync(0xffffffffu, s2, 2);
        l1 = l1 * al1 + s1;
        l2 = l2 * al2 + s2;

        // Rescale O
#pragma unroll
        for (int nt = 0; nt < 8; nt++) {
            O[nt][0] *= al1; O[nt][1] *= al1;
            O[nt][2] *= al2; O[nt][3] *= al2;
        }

        // ---- O += P @ V : contraction over 64 keys, output 64 d-cols ----
#pragma unroll
        for (int s = 0; s < 4; s++) {
            uint32_t bf[8][2];
#pragma unroll
            for (int g = 0; g < 4; g++) {
                uint32_t r[4];
                ldsm4t(r, vb + (s * 16 + v_r) * (FA_ASTR * 2) + (g * 16 + v_c) * 2);
                bf[2 * g][0] = r[0]; bf[2 * g][1] = r[1];
                bf[2 * g + 1][0] = r[2]; bf[2 * g + 1][1] = r[3];
            }
#pragma unroll
            for (int nt = 0; nt < 8; nt++)
                mma16816h(O[nt], ph[s], bf[nt]);
        }

        CP_WAIT0();        // prefetch landed (no-op on last iteration)
        __syncthreads();   // next tile visible; all warps done with old buffer
    }

    // Finalize -> fp16 out
    const float li1 = 1.f / l1;
    const float li2 = 1.f / l2;
    __half* op = out + ((size_t)b * SEQ + q0) * DMODEL + h * HDIM;
#pragma unroll
    for (int nt = 0; nt < 8; nt++) {
        int c = nt * 8 + q4 * 2;
        *(uint32_t*)(op + (size_t)row1 * DMODEL + c) =
            pack_h2(O[nt][0] * li1, O[nt][1] * li1);
        *(uint32_t*)(op + (size_t)row2 * DMODEL + c) =
            pack_h2(O[nt][2] * li2, O[nt][3] * li2);
    }
}

// ===========================================================================
// Launch
// ===========================================================================
extern "C" void kernel_launch(void* const* d_in, const int* in_sizes, int n_in,
                              void* d_out, int out_size) {
    const float* x    = (const float*)d_in[0];
    // d_in[1] = mask (tril) — causality applied analytically
    const float* Wqkv = (const float*)d_in[2];
    const float* Wout = (const float*)d_in[3];
    float* out = (float*)d_out;

    __half *xh, *qkv, *attnh, *wqkvT, *woutT;
    cudaGetSymbolAddress((void**)&xh, g_xh);
    cudaGetSymbolAddress((void**)&qkv, g_qkv);
    cudaGetSymbolAddress((void**)&attnh, g_attnh);
    cudaGetSymbolAddress((void**)&wqkvT, g_wqkvT);
    cudaGetSymbolAddress((void**)&woutT, g_woutT);

    cudaFuncSetAttribute(gemm_mma<true>, cudaFuncAttributeMaxDynamicSharedMemorySize,
                         GEMM_SMEM);
    cudaFuncSetAttribute(gemm_mma<false>, cudaFuncAttributeMaxDynamicSharedMemorySize,
                         GEMM_SMEM);
    cudaFuncSetAttribute(attn_mma, cudaFuncAttributeMaxDynamicSharedMemorySize,
                         FA_SMEM);

    // 1. Convert inputs to fp16
    conv_h<<<(ROWS * DMODEL / 4) / 256, 256>>>(x, xh);
    transp_h<<<dim3(N3 / 32, DMODEL / 32), dim3(32, 8)>>>(Wqkv, wqkvT, DMODEL, N3);
    transp_h<<<dim3(DMODEL / 32, DMODEL / 32), dim3(32, 8)>>>(Wout, woutT, DMODEL, DMODEL);

    // 2. QKV projection (fp16 HMMA, K=1024), fp16 out
    gemm_mma<true><<<dim3(N3 / 128, ROWS / 128), 256, GEMM_SMEM>>>(xh, wqkvT, qkv,
                                                                   N3, DMODEL);

    // 3. Causal flash attention (fp16 tensor cores, FA2 layout), fp16 out
    attn_mma<<<dim3(SEQ / 64, NHEADS, BATCH), 128, FA_SMEM>>>(qkv, attnh);

    // 4. Output projection (fp16 HMMA, K=1024), fp32 out
    gemm_mma<false><<<dim3(DMODEL / 128, ROWS / 128), 256, GEMM_SMEM>>>(attnh, woutT, out,
                                                                        DMODEL, DMODEL);
}